// round 7
// baseline (speedup 1.0000x reference)
#include <cuda_runtime.h>
#include <math.h>

// Problem constants  (B,F,T,C = 8192, 256, 32, 100)
#define BN 8192
#define FF 256
#define TT 32
#define NI 63
#define NL 64
#define CC 100
#define CPAD 128   // padded class dim

#define BM 64      // batch rows per CTA
#define KC 128     // k-chunk for W staging
#define TPP 2      // trees per pass
#define NPASS (TT / TPP)

// smem strides (floats)
#define XS4 260    // xsT row stride   (1040 B; rows broadcast-read)
#define WS4 132    // wsT col stride   (528 B;  ≡4 mod 32 → conflict-free)
#define PLS 65     // plT row stride   (scalar access)
#define LPS 68     // lpT row stride   (272 B; ≡4 mod 32; float4-read)
#define MSS 68     // MsS class stride

// smem offsets (floats)
#define OFF_XS 0                         // 64*260            = 16640
#define OFF_R1 16640                     // max(wsT 128*132=16896, lpT 2*64*68=8704)
#define OFF_R2 (OFF_R1 + 16896)          // max(plT 2*64*65=8320, MsS 128*68=8704)
#define OFF_SB (OFF_R2 + 8704)           // 128
#define SMEM_FLOATS (OFF_SB + 128)
#define SMEM_BYTES (SMEM_FLOATS * 4)     // ~169.5 KB

// packed f32x2 FMA (sm_103a FFMA2)
#define FMA2(acc, a, b) \
    asm("fma.rn.f32x2 %0, %1, %2, %3;" : "=l"(acc) : "l"(a), "l"(b), "l"(acc))

__device__ __forceinline__ float pair_sum(unsigned long long u) {
    return __uint_as_float((unsigned)u) + __uint_as_float((unsigned)(u >> 32));
}

// ---------------- scratch ----------------------------------------------------
__device__ float g_scalars[4];                  // [0] = inv_temp
__device__ float g_w[TT];                       // softmax(tree_weights)
__device__ float g_MsT[TT * CPAD * NL];         // transposed: [t][class][leaf]

// ---------------- prep 0 -----------------------------------------------------
__global__ void prep0_kernel(const float* __restrict__ tw,
                             const float* __restrict__ log_temp) {
    if (threadIdx.x != 0 || blockIdx.x != 0) return;
    float temp = expf(log_temp[0]);
    temp = fminf(fmaxf(temp, 0.1f), 5.0f);
    g_scalars[0] = 1.0f / temp;
    float mx = -INFINITY;
    for (int t = 0; t < TT; t++) mx = fmaxf(mx, tw[t]);
    float sum = 0.0f;
    for (int t = 0; t < TT; t++) sum += expf(tw[t] - mx);
    float inv = 1.0f / sum;
    for (int t = 0; t < TT; t++) g_w[t] = expf(tw[t] - mx) * inv;
}

// ---------------- prep 1: MsT[t][c][l] = w[t]*softmax(leaf_logits/temp)[c] --
__global__ void prep1_kernel(const float* __restrict__ leaf_logits) {
    __shared__ float sv[CPAD];
    __shared__ float s_mx, s_invsum, s_w;
    int blk = blockIdx.x;          // t*64 + l
    int t = blk >> 6;
    int l = blk & 63;
    int c = threadIdx.x;           // 0..127
    float v = (c < CC) ? leaf_logits[(size_t)blk * CC + c] * g_scalars[0]
                       : -INFINITY;
    sv[c] = v;
    __syncthreads();
    if (c == 0) {
        float mx = -INFINITY;
        for (int i = 0; i < CC; i++) mx = fmaxf(mx, sv[i]);
        float sum = 0.0f;
        for (int i = 0; i < CC; i++) sum += expf(sv[i] - mx);
        s_mx = mx;
        s_invsum = 1.0f / sum;
        s_w = g_w[t];
    }
    __syncthreads();
    float r = (c < CC) ? s_w * expf(v - s_mx) * s_invsum : 0.0f;
    g_MsT[((size_t)t * CPAD + c) * NL + l] = r;
}

// ---------------- main fused kernel -----------------------------------------
__global__ __launch_bounds__(256, 1)
void main_kernel(const float* __restrict__ x,
                 const float* __restrict__ W,
                 const float* __restrict__ split_bias,
                 float* __restrict__ out) {
    extern __shared__ float sm[];
    float* xsT = sm + OFF_XS;   // [row][k]           stride 260 (full K)
    float* R1  = sm + OFF_R1;   // wsT [col][kchunk] s132  |  lpT [tr][row][leaf] s68
    float* R2  = sm + OFF_R2;   // plT [tr][row][node] s65 |  MsS [class][leaf] s68
    float* sb  = sm + OFF_SB;   // [col 0..127] bias for the 2 trees of this pass

    const int tid = threadIdx.x;
    const int tx5 = tid & 31;         // 0..31
    const int ty3 = tid >> 5;         // 0..7  (== warp id)
    const int rowBase = blockIdx.x * BM;
    const float inv_temp = g_scalars[0];

    // ---- load x tile (row-major, coalesced, full K resident) ----
    {
        const int r = tid >> 2, q = tid & 3;
        const float* xrow = x + (size_t)(rowBase + r) * FF;
        float* dst = xsT + r * XS4;
#pragma unroll
        for (int m = 0; m < 16; m++) {
            int c4 = (q + m * 4) * 4;
            *(float4*)(dst + c4) = *(const float4*)(xrow + c4);
        }
    }

    unsigned long long outAcc2[8][4];   // [row i][class group jc], L-paired
#pragma unroll
    for (int i = 0; i < 8; i++)
#pragma unroll
        for (int j = 0; j < 4; j++) outAcc2[i][j] = 0ULL;

    for (int pass = 0; pass < NPASS; pass++) {
        const int t0 = pass * TPP;

        // ---- phase 1: logits GEMM for 2 trees (64 rows x 128 cols, K=256) --
        unsigned long long acc2[8][4];  // [row i][col j], K-paired
#pragma unroll
        for (int i = 0; i < 8; i++)
#pragma unroll
            for (int j = 0; j < 4; j++) acc2[i][j] = 0ULL;

#pragma unroll
        for (int kc = 0; kc < FF / KC; kc++) {
            __syncthreads();   // prev consumers of R1 done
            // load W chunk: col = tid>>1 (2 trees x 64 node slots), half k
            {
                const int col = tid >> 1;
                const int half = tid & 1;
                const int gt = t0 + (col >> 6);
                const int node = col & 63;
                const bool real = (node < NI);
                const float* src = W + ((size_t)gt * NI + node) * FF + kc * KC + half * 64;
                float* dst = R1 + col * WS4 + half * 64;
#pragma unroll
                for (int m = 0; m < 16; m++) {
                    float4 v = real ? *(const float4*)(src + m * 4)
                                    : make_float4(0.f, 0.f, 0.f, 0.f);
                    *(float4*)(dst + m * 4) = v;
                }
            }
            if (kc == 0 && tid < 128) {
                int gt = t0 + (tid >> 6);
                int node = tid & 63;
                sb[tid] = (node < NI) ? split_bias[gt * NI + node] : 0.0f;
            }
            __syncthreads();

            const float* xbase = xsT + kc * KC;
#pragma unroll 2
            for (int kg = 0; kg < KC; kg += 4) {
                unsigned long long b01[4], b23[4];
#pragma unroll
                for (int j = 0; j < 4; j++) {
                    float4 v = *(const float4*)(R1 + (tx5 + 32 * j) * WS4 + kg);
                    b01[j] = *(const unsigned long long*)&v.x;
                    b23[j] = *(const unsigned long long*)&v.z;
                }
#pragma unroll
                for (int i = 0; i < 8; i++) {
                    float4 va = *(const float4*)(xbase + (ty3 + 8 * i) * XS4 + kg);
                    unsigned long long a01 = *(const unsigned long long*)&va.x;
                    unsigned long long a23 = *(const unsigned long long*)&va.z;
#pragma unroll
                    for (int j = 0; j < 4; j++) {
                        FMA2(acc2[i][j], a01, b01[j]);
                        FMA2(acc2[i][j], a23, b23[j]);
                    }
                }
            }
        }

        // sigmoid + write split probs: plT[tr][row][node] in R2
#pragma unroll
        for (int j = 0; j < 4; j++) {
            int col = tx5 + 32 * j;
            int tr = col >> 6;
            int node = col & 63;
            float bias = sb[col];
#pragma unroll
            for (int i = 0; i < 8; i++) {
                float z = (pair_sum(acc2[i][j]) + bias) * inv_temp;
                float p = 1.0f / (1.0f + __expf(-z));
                R2[tr * (64 * PLS) + (ty3 + 8 * i) * PLS + node] = p;
            }
        }
        __syncthreads();

        // ---- phase 2: leaf probs (heap climb) -> lpT[tr][row][leaf] in R1 --
        for (int e = tid; e < TPP * NL * BM; e += 256) {
            int leaf = e & 63;
            int row = (e >> 6) & 63;
            int tr = e >> 12;
            const float* pl = R2 + tr * (64 * PLS) + row * PLS;
            int node = leaf + NI;
            float p = 1.0f;
#pragma unroll
            for (int d = 0; d < 6; d++) {
                int parent = (node - 1) >> 1;
                float g = pl[parent];
                p *= ((node & 1) == 0) ? g : (1.0f - g);
                node = parent;
            }
            R1[tr * (64 * LPS) + row * LPS + leaf] = p;
        }
        __syncthreads();

        // ---- phase 3: out += leafP @ M, per tree ----
#pragma unroll
        for (int tr = 0; tr < TPP; tr++) {
            // load MsS [class][leaf] for tree t0+tr into R2 (plT consumed)
            for (int idx = tid; idx < CPAD * 16; idx += 256) {
                int c = idx >> 4;
                int l4 = (idx & 15) << 2;
                *(float4*)(R2 + c * MSS + l4) =
                    *(const float4*)(g_MsT + ((size_t)(t0 + tr) * CPAD + c) * NL + l4);
            }
            __syncthreads();

            const float* lp = R1 + tr * (64 * LPS);
#pragma unroll 2
            for (int l = 0; l < NL; l += 4) {
                unsigned long long b01[4], b23[4];
#pragma unroll
                for (int j = 0; j < 4; j++) {
                    float4 v = *(const float4*)(R2 + (tx5 + 32 * j) * MSS + l);
                    b01[j] = *(const unsigned long long*)&v.x;
                    b23[j] = *(const unsigned long long*)&v.z;
                }
#pragma unroll
                for (int i = 0; i < 8; i++) {
                    float4 va = *(const float4*)(lp + (ty3 + 8 * i) * LPS + l);
                    unsigned long long a01 = *(const unsigned long long*)&va.x;
                    unsigned long long a23 = *(const unsigned long long*)&va.z;
#pragma unroll
                    for (int j = 0; j < 4; j++) {
                        FMA2(outAcc2[i][j], a01, b01[j]);
                        FMA2(outAcc2[i][j], a23, b23[j]);
                    }
                }
            }
            __syncthreads();   // before MsS reload / next pass W load
        }
    }

    // ---- epilogue ----
#pragma unroll
    for (int i = 0; i < 8; i++) {
        int row = rowBase + ty3 + 8 * i;
        float* op = out + (size_t)row * CC;
#pragma unroll
        for (int j = 0; j < 4; j++) {
            int c = tx5 + 32 * j;
            if (c < CC) op[c] = pair_sum(outAcc2[i][j]);
        }
    }
}

// ---------------- launch -----------------------------------------------------
extern "C" void kernel_launch(void* const* d_in, const int* in_sizes, int n_in,
                              void* d_out, int out_size) {
    const float* x          = nullptr;   // 2097152
    const float* split_w    = nullptr;   // 516096
    const float* split_bias = nullptr;   // 2016
    const float* leaf_log   = nullptr;   // 204800
    const float* tree_w     = nullptr;   // 32
    const float* log_temp   = nullptr;   // 1
    for (int i = 0; i < n_in; i++) {
        switch (in_sizes[i]) {
            case BN * FF:      x          = (const float*)d_in[i]; break;
            case TT * NI * FF: split_w    = (const float*)d_in[i]; break;
            case TT * NI:      split_bias = (const float*)d_in[i]; break;
            case TT * NL * CC: leaf_log   = (const float*)d_in[i]; break;
            case TT:           tree_w     = (const float*)d_in[i]; break;
            case 1:            log_temp   = (const float*)d_in[i]; break;
            default: break;
        }
    }
    if (!x)          x          = (const float*)d_in[0];
    if (!split_w)    split_w    = (const float*)d_in[1];
    if (!split_bias) split_bias = (const float*)d_in[2];
    if (!leaf_log)   leaf_log   = (const float*)d_in[3];
    if (!tree_w)     tree_w     = (const float*)d_in[4];
    if (!log_temp)   log_temp   = (const float*)d_in[5];
    float* out = (float*)d_out;

    prep0_kernel<<<1, 32>>>(tree_w, log_temp);
    prep1_kernel<<<TT * NL, CPAD>>>(leaf_log);

    cudaFuncSetAttribute(main_kernel,
                         cudaFuncAttributeMaxDynamicSharedMemorySize, SMEM_BYTES);
    main_kernel<<<BN / BM, 256, SMEM_BYTES>>>(x, split_w, split_bias, out);
}

// round 9
// speedup vs baseline: 2.6181x; 2.6181x over previous
#include <cuda_runtime.h>
#include <math.h>
#include <stdint.h>

// Problem constants  (B,F,T,C = 8192, 256, 32, 100)
#define BN 8192
#define FF 256
#define TT 32
#define NI 63
#define NL 64
#define CC 100
#define CPAD 128

#define BM 128            // batch rows per CTA
#define NHALF 2
#define TPH (TT / NHALF)  // 16 trees per CTA

// smem strides (floats): fragment loads need stride ≡ 4 (mod 32)
#define XS 260
#define WS 260
#define PLS 65            // scalar-only
#define LPS 68
#define MSS 68

// smem byte offsets
#define OFF_X 0                            // 128*260*4 = 133120
#define OFF_R 133120                       // region, 71680 B:
                                           //   wsT  @R+0      64*260*4  = 66560
                                           //   plT  @R+0      128*65*4  = 33280
                                           //   Ms   @R+0      128*68*4  = 34816
                                           //   lpT  @R+36864  128*68*4  = 34816
#define OFF_LP (OFF_R + 36864)
#define OFF_BIAS (OFF_R + 71680)           // 204800
#define SMEM_BYTES (OFF_BIAS + 256)        // 205056

__device__ __forceinline__ float rna_tf32(float f) {
    uint32_t u;
    asm("cvt.rna.tf32.f32 %0, %1;" : "=r"(u) : "f"(f));
    return __uint_as_float(u);
}

__device__ __forceinline__ void mma8(float d[4], const uint32_t a[4], const uint32_t b[2]) {
    asm volatile(
        "mma.sync.aligned.m16n8k8.row.col.f32.tf32.tf32.f32 "
        "{%0,%1,%2,%3}, {%4,%5,%6,%7}, {%8,%9}, {%0,%1,%2,%3};"
        : "+f"(d[0]), "+f"(d[1]), "+f"(d[2]), "+f"(d[3])
        : "r"(a[0]), "r"(a[1]), "r"(a[2]), "r"(a[3]), "r"(b[0]), "r"(b[1]));
}

// ---------------- scratch ----------------------------------------------------
__device__ float g_scalars[4];
__device__ float g_w[TT];
__device__ float g_MsT[TT * CPAD * NL];   // [t][class(128)][leaf(64)], tf32-rounded
__device__ float g_part[NHALF * BN * CC];

// ---------------- prep 0 -----------------------------------------------------
__global__ void prep0_kernel(const float* __restrict__ tw,
                             const float* __restrict__ log_temp) {
    if (threadIdx.x != 0 || blockIdx.x != 0) return;
    float temp = expf(log_temp[0]);
    temp = fminf(fmaxf(temp, 0.1f), 5.0f);
    g_scalars[0] = 1.0f / temp;
    float mx = -INFINITY;
    for (int t = 0; t < TT; t++) mx = fmaxf(mx, tw[t]);
    float s = 0.0f;
    for (int t = 0; t < TT; t++) s += expf(tw[t] - mx);
    float inv = 1.0f / s;
    for (int t = 0; t < TT; t++) g_w[t] = expf(tw[t] - mx) * inv;
}

// ---------------- prep 1: MsT[t][c][l] = w[t]*softmax(leaf_logits/temp)[c] --
__global__ void prep1_kernel(const float* __restrict__ leaf_logits) {
    __shared__ float sv[CPAD];
    __shared__ float s_mx, s_inv, s_w;
    int blk = blockIdx.x;           // t*64 + l
    int t = blk >> 6, l = blk & 63;
    int c = threadIdx.x;            // 0..127
    float v = (c < CC) ? leaf_logits[(size_t)blk * CC + c] * g_scalars[0] : -INFINITY;
    sv[c] = v;
    __syncthreads();
    if (c == 0) {
        float mx = -INFINITY;
        for (int i = 0; i < CC; i++) mx = fmaxf(mx, sv[i]);
        float s = 0.0f;
        for (int i = 0; i < CC; i++) s += expf(sv[i] - mx);
        s_mx = mx; s_inv = 1.0f / s; s_w = g_w[t];
    }
    __syncthreads();
    float r = (c < CC) ? s_w * expf(v - s_mx) * s_inv : 0.0f;
    g_MsT[((size_t)t * CPAD + c) * NL + l] = rna_tf32(r);
}

// ---------------- main kernel ------------------------------------------------
__global__ __launch_bounds__(256, 1)
void main_kernel(const float* __restrict__ x,
                 const float* __restrict__ W,
                 const float* __restrict__ split_bias) {
    extern __shared__ float sm[];
    char* smc = (char*)sm;
    float* Xs   = (float*)(smc + OFF_X);     // [row][k]      stride 260
    float* wsT  = (float*)(smc + OFF_R);     // [node][k]     stride 260
    float* plT  = (float*)(smc + OFF_R);     // [row][node]   stride 65
    float* Ms   = (float*)(smc + OFF_R);     // [class][leaf] stride 68
    float* lpT  = (float*)(smc + OFF_LP);    // [row][leaf]   stride 68
    float* bias = (float*)(smc + OFF_BIAS);
    const uint32_t* Xu  = (const uint32_t*)Xs;
    const uint32_t* Wu  = (const uint32_t*)wsT;
    const uint32_t* Lu  = (const uint32_t*)lpT;
    const uint32_t* Mu  = (const uint32_t*)Ms;

    const int tid = threadIdx.x;
    const int wid = tid >> 5;
    const int lane = tid & 31;
    const int g = lane >> 2;          // groupID 0..7
    const int tg = lane & 3;          // threadID_in_group 0..3
    const int wr = wid & 3;           // warp row block (32 rows)
    const int wc = wid >> 2;          // warp col block
    const int rowBase = blockIdx.x * BM;
    const int half = blockIdx.y;
    const float inv_temp = g_scalars[0];

    // ---- stage X tile (tf32-rounded) ----
#pragma unroll
    for (int m = 0; m < 32; m++) {
        int idx4 = tid + m * 256;          // row*64 + kc
        int row = idx4 >> 6, kc = idx4 & 63;
        float4 v = *(const float4*)(x + (size_t)(rowBase + row) * FF + kc * 4);
        v.x = rna_tf32(v.x); v.y = rna_tf32(v.y);
        v.z = rna_tf32(v.z); v.w = rna_tf32(v.w);
        *(float4*)(Xs + row * XS + kc * 4) = v;
    }

    float d2[2][8][4];
#pragma unroll
    for (int mi = 0; mi < 2; mi++)
#pragma unroll
        for (int ni = 0; ni < 8; ni++)
#pragma unroll
            for (int e = 0; e < 4; e++) d2[mi][ni][e] = 0.0f;

    for (int tt = 0; tt < TPH; tt++) {
        const int t = half * TPH + tt;
        __syncthreads();   // region R reuse (prev phase-3 / X staging visible)

        // ---- load W tile (tf32-rounded); node 63 zero pad ----
#pragma unroll
        for (int m = 0; m < 16; m++) {
            int idx4 = tid + m * 256;
            int node = idx4 >> 6, kc = idx4 & 63;
            float4 v;
            if (node < NI) {
                v = *(const float4*)(W + ((size_t)t * NI + node) * FF + kc * 4);
                v.x = rna_tf32(v.x); v.y = rna_tf32(v.y);
                v.z = rna_tf32(v.z); v.w = rna_tf32(v.w);
            } else {
                v = make_float4(0.f, 0.f, 0.f, 0.f);
            }
            *(float4*)(wsT + node * WS + kc * 4) = v;
        }
        if (tid < 64) bias[tid] = (tid < NI) ? split_bias[t * NI + tid] : 0.0f;
        __syncthreads();

        // ---- GEMM1: D1 = X @ W^T (128x64, K=256), warp tile 32x32 ----
        float d1[2][4][4];
#pragma unroll
        for (int mi = 0; mi < 2; mi++)
#pragma unroll
            for (int ni = 0; ni < 4; ni++)
#pragma unroll
                for (int e = 0; e < 4; e++) d1[mi][ni][e] = 0.0f;

#pragma unroll 4
        for (int ks = 0; ks < 32; ks++) {
            const int k0 = ks * 8;
            uint32_t a[2][4], b[4][2];
#pragma unroll
            for (int mi = 0; mi < 2; mi++) {
                int r0 = wr * 32 + mi * 16 + g;
                a[mi][0] = Xu[r0 * XS + k0 + tg];
                a[mi][1] = Xu[(r0 + 8) * XS + k0 + tg];
                a[mi][2] = Xu[r0 * XS + k0 + tg + 4];
                a[mi][3] = Xu[(r0 + 8) * XS + k0 + tg + 4];
            }
#pragma unroll
            for (int ni = 0; ni < 4; ni++) {
                int n0 = wc * 32 + ni * 8 + g;
                b[ni][0] = Wu[n0 * WS + k0 + tg];
                b[ni][1] = Wu[n0 * WS + k0 + tg + 4];
            }
#pragma unroll
            for (int mi = 0; mi < 2; mi++)
#pragma unroll
                for (int ni = 0; ni < 4; ni++) mma8(d1[mi][ni], a[mi], b[ni]);
        }
        __syncthreads();   // wsT dead → plT region free

        // ---- sigmoid + write plT[row][node] ----
#pragma unroll
        for (int mi = 0; mi < 2; mi++) {
            int r0 = wr * 32 + mi * 16 + g;
#pragma unroll
            for (int ni = 0; ni < 4; ni++) {
                int n0 = wc * 32 + ni * 8 + 2 * tg;
#pragma unroll
                for (int e = 0; e < 4; e++) {
                    int r = r0 + (e >> 1) * 8;
                    int n = n0 + (e & 1);
                    float z = (d1[mi][ni][e] + bias[n]) * inv_temp;
                    plT[r * PLS + n] = 1.0f / (1.0f + __expf(-z));
                }
            }
        }
        __syncthreads();

        // ---- phase 2: heap climb -> lpT[row][leaf] (tf32-rounded) ----
        for (int e = tid; e < NL * BM; e += 256) {
            int leaf = e & 63;
            int row = e >> 6;
            int node = leaf + NI;
            float p = 1.0f;
#pragma unroll
            for (int d = 0; d < 6; d++) {
                int parent = (node - 1) >> 1;
                float gg = plT[row * PLS + parent];
                p *= ((node & 1) == 0) ? gg : (1.0f - gg);
                node = parent;
            }
            lpT[row * LPS + leaf] = rna_tf32(p);
        }
        __syncthreads();   // plT dead → Ms region free

        // ---- load Ms[class][leaf] ----
#pragma unroll
        for (int m = 0; m < 8; m++) {
            int idx4 = tid + m * 256;          // class*16 + l4
            int c = idx4 >> 4, l4 = (idx4 & 15) * 4;
            *(float4*)(Ms + c * MSS + l4) =
                *(const float4*)(g_MsT + ((size_t)t * CPAD + c) * NL + l4);
        }
        __syncthreads();

        // ---- GEMM2: D2 += leafP @ Ms^T (128x128, K=64), warp tile 32x64 ----
#pragma unroll
        for (int ks = 0; ks < 8; ks++) {
            const int k0 = ks * 8;
            uint32_t a[2][4], b[8][2];
#pragma unroll
            for (int mi = 0; mi < 2; mi++) {
                int r0 = wr * 32 + mi * 16 + g;
                a[mi][0] = Lu[r0 * LPS + k0 + tg];
                a[mi][1] = Lu[(r0 + 8) * LPS + k0 + tg];
                a[mi][2] = Lu[r0 * LPS + k0 + tg + 4];
                a[mi][3] = Lu[(r0 + 8) * LPS + k0 + tg + 4];
            }
#pragma unroll
            for (int ni = 0; ni < 8; ni++) {
                int n0 = wc * 64 + ni * 8 + g;
                b[ni][0] = Mu[n0 * MSS + k0 + tg];
                b[ni][1] = Mu[n0 * MSS + k0 + tg + 4];
            }
#pragma unroll
            for (int mi = 0; mi < 2; mi++)
#pragma unroll
                for (int ni = 0; ni < 8; ni++) mma8(d2[mi][ni], a[mi], b[ni]);
        }
    }

    // ---- epilogue: store partials (c0/c1 pairs = contiguous cols) ----
#pragma unroll
    for (int mi = 0; mi < 2; mi++) {
#pragma unroll
        for (int e2 = 0; e2 < 2; e2++) {       // 0: c0/c1 row, 1: c2/c3 row+8
            int row = rowBase + wr * 32 + mi * 16 + g + e2 * 8;
            float* op = g_part + (size_t)half * (BN * CC) + (size_t)row * CC;
#pragma unroll
            for (int ni = 0; ni < 8; ni++) {
                int col = wc * 64 + ni * 8 + 2 * tg;
                if (col + 1 < CC) {
                    *(float2*)(op + col) =
                        make_float2(d2[mi][ni][e2 * 2], d2[mi][ni][e2 * 2 + 1]);
                } else if (col < CC) {
                    op[col] = d2[mi][ni][e2 * 2];
                }
            }
        }
    }
}

// ---------------- reduce -----------------------------------------------------
__global__ void reduce_kernel(float* __restrict__ out) {
    int i = blockIdx.x * blockDim.x + threadIdx.x;
    if (i >= BN * CC) return;
    out[i] = g_part[i] + g_part[BN * CC + i];
}

// ---------------- launch -----------------------------------------------------
extern "C" void kernel_launch(void* const* d_in, const int* in_sizes, int n_in,
                              void* d_out, int out_size) {
    const float* x          = nullptr;   // 2097152
    const float* split_w    = nullptr;   // 516096
    const float* split_bias = nullptr;   // 2016
    const float* leaf_log   = nullptr;   // 204800
    const float* tree_w     = nullptr;   // 32
    const float* log_temp   = nullptr;   // 1
    for (int i = 0; i < n_in; i++) {
        switch (in_sizes[i]) {
            case BN * FF:      x          = (const float*)d_in[i]; break;
            case TT * NI * FF: split_w    = (const float*)d_in[i]; break;
            case TT * NI:      split_bias = (const float*)d_in[i]; break;
            case TT * NL * CC: leaf_log   = (const float*)d_in[i]; break;
            case TT:           tree_w     = (const float*)d_in[i]; break;
            case 1:            log_temp   = (const float*)d_in[i]; break;
            default: break;
        }
    }
    if (!x)          x          = (const float*)d_in[0];
    if (!split_w)    split_w    = (const float*)d_in[1];
    if (!split_bias) split_bias = (const float*)d_in[2];
    if (!leaf_log)   leaf_log   = (const float*)d_in[3];
    if (!tree_w)     tree_w     = (const float*)d_in[4];
    if (!log_temp)   log_temp   = (const float*)d_in[5];
    float* out = (float*)d_out;

    prep0_kernel<<<1, 32>>>(tree_w, log_temp);
    prep1_kernel<<<TT * NL, CPAD>>>(leaf_log);

    cudaFuncSetAttribute(main_kernel,
                         cudaFuncAttributeMaxDynamicSharedMemorySize, SMEM_BYTES);
    dim3 grid(BN / BM, NHALF);
    main_kernel<<<grid, 256, SMEM_BYTES>>>(x, split_w, split_bias);

    reduce_kernel<<<(BN * CC + 255) / 256, 256>>>(out);
}

// round 10
// speedup vs baseline: 2.9527x; 1.1278x over previous
#include <cuda_runtime.h>
#include <math.h>
#include <stdint.h>

// Problem constants  (B,F,T,C = 8192, 256, 32, 100)
#define BN 8192
#define FF 256
#define TT 32
#define NI 63
#define NL 64
#define CC 100
#define CPAD 128

#define BM 128            // batch rows per CTA
#define NHALF 2
#define TPH (TT / NHALF)  // 16 trees per CTA

// smem strides (floats)
#define XS 260            // X row stride   (≡4 mod 32)
#define WS 132            // wsT node stride within a K=128 chunk (≡4 mod 32)
#define PLS 65            // plT row stride (scalar access)
#define LPS 68            // lpT row stride (≡4 mod 32)
#define MSS 68            // Ms class stride

// smem byte offsets
#define OFF_X 0                       // 128*260*4 = 133120
#define OFF_R 133120                  // two 34816-B buffers:
#define BUFB 34816                    //  buf c at OFF_R + c*BUFB
                                      //  buf0: W chunk0 (64*132*4=33792) -> plT(128*65*4=33280) -> Ms(128*68*4=34816)
                                      //  buf1: W chunk1 -> lpT(128*68*4=34816)
#define OFF_BIAS (OFF_R + 2 * BUFB)   // 202752
#define SMEM_BYTES (OFF_BIAS + 256)   // 203008

__device__ __forceinline__ float rna_tf32(float f) {
    uint32_t u;
    asm("cvt.rna.tf32.f32 %0, %1;" : "=r"(u) : "f"(f));
    return __uint_as_float(u);
}
__device__ __forceinline__ uint32_t smem_u32(const void* p) {
    uint32_t a;
    asm("{ .reg .u64 t; cvta.to.shared.u64 t, %1; cvt.u32.u64 %0, t; }" : "=r"(a) : "l"(p));
    return a;
}
#define CP_ASYNC16(dst, src, sz) \
    asm volatile("cp.async.cg.shared.global [%0], [%1], 16, %2;" \
                 :: "r"(dst), "l"(src), "r"(sz) : "memory")
#define CP_COMMIT() asm volatile("cp.async.commit_group;" ::: "memory")
#define CP_WAIT1()  asm volatile("cp.async.wait_group 1;" ::: "memory")
#define CP_WAIT0()  asm volatile("cp.async.wait_group 0;" ::: "memory")

__device__ __forceinline__ void mma8(float d[4], const uint32_t a[4], const uint32_t b[2]) {
    asm volatile(
        "mma.sync.aligned.m16n8k8.row.col.f32.tf32.tf32.f32 "
        "{%0,%1,%2,%3}, {%4,%5,%6,%7}, {%8,%9}, {%0,%1,%2,%3};"
        : "+f"(d[0]), "+f"(d[1]), "+f"(d[2]), "+f"(d[3])
        : "r"(a[0]), "r"(a[1]), "r"(a[2]), "r"(a[3]), "r"(b[0]), "r"(b[1]));
}

// ---------------- scratch ----------------------------------------------------
__device__ float g_scalars[4];
__device__ float g_MsT[TT * CPAD * NL];   // [t][class(128)][leaf(64)], tf32-rounded
__device__ float g_part[NHALF * BN * CC];

// ---------------- prep (merged): per-block tree softmax + Ms build ----------
__global__ void prep_kernel(const float* __restrict__ leaf_logits,
                            const float* __restrict__ tw,
                            const float* __restrict__ log_temp) {
    __shared__ float sv[CPAD];
    __shared__ float s_mx, s_inv, s_w, s_it;
    int blk = blockIdx.x;           // t*64 + l
    int t = blk >> 6, l = blk & 63;
    int c = threadIdx.x;            // 0..127
    if (c == 0) {
        float temp = expf(log_temp[0]);
        temp = fminf(fmaxf(temp, 0.1f), 5.0f);
        float it = 1.0f / temp;
        s_it = it;
        if (blk == 0) g_scalars[0] = it;
        // tree-weight softmax (32 wide), computed redundantly per block
        float mx = -INFINITY;
        for (int i = 0; i < TT; i++) mx = fmaxf(mx, tw[i]);
        float s = 0.0f;
        for (int i = 0; i < TT; i++) s += expf(tw[i] - mx);
        s_w = expf(tw[t] - mx) / s;
    }
    __syncthreads();
    float v = (c < CC) ? leaf_logits[(size_t)blk * CC + c] * s_it : -INFINITY;
    sv[c] = v;
    __syncthreads();
    if (c == 0) {
        float mx = -INFINITY;
        for (int i = 0; i < CC; i++) mx = fmaxf(mx, sv[i]);
        float s = 0.0f;
        for (int i = 0; i < CC; i++) s += expf(sv[i] - mx);
        s_mx = mx; s_inv = 1.0f / s;
    }
    __syncthreads();
    float r = (c < CC) ? s_w * expf(v - s_mx) * s_inv : 0.0f;
    g_MsT[((size_t)t * CPAD + c) * NL + l] = rna_tf32(r);
}

// ---------------- main kernel ------------------------------------------------
__global__ __launch_bounds__(256, 1)
void main_kernel(const float* __restrict__ x,
                 const float* __restrict__ W,
                 const float* __restrict__ split_bias) {
    extern __shared__ float sm[];
    char* smc = (char*)sm;
    const uint32_t sb32 = smem_u32(sm);
    float* Xs   = (float*)(smc + OFF_X);
    float* buf0 = (float*)(smc + OFF_R);
    float* buf1 = (float*)(smc + OFF_R + BUFB);
    float* plT  = buf0;                      // [row][node]   stride 65
    float* lpT  = buf1;                      // [row][leaf]   stride 68
    float* Ms   = buf0;                      // [class][leaf] stride 68
    float* bias = (float*)(smc + OFF_BIAS);
    const uint32_t* Xu = (const uint32_t*)Xs;
    const uint32_t* Lu = (const uint32_t*)lpT;
    const uint32_t* Mu = (const uint32_t*)Ms;

    const int tid = threadIdx.x;
    const int wid = tid >> 5;
    const int lane = tid & 31;
    const int g = lane >> 2;
    const int tg = lane & 3;
    const int wr = wid & 3;
    const int wc = wid >> 2;
    const int rowBase = blockIdx.x * BM;
    const int half = blockIdx.y;
    const float inv_temp = g_scalars[0];

    // ---- stage X tile (tf32-rounded) ----
#pragma unroll
    for (int m = 0; m < 32; m++) {
        int idx4 = tid + m * 256;
        int row = idx4 >> 6, kc = idx4 & 63;
        float4 v = *(const float4*)(x + (size_t)(rowBase + row) * FF + kc * 4);
        v.x = rna_tf32(v.x); v.y = rna_tf32(v.y);
        v.z = rna_tf32(v.z); v.w = rna_tf32(v.w);
        *(float4*)(Xs + row * XS + kc * 4) = v;
    }

    float d2[2][8][4];
#pragma unroll
    for (int mi = 0; mi < 2; mi++)
#pragma unroll
        for (int ni = 0; ni < 8; ni++)
#pragma unroll
            for (int e = 0; e < 4; e++) d2[mi][ni][e] = 0.0f;

    for (int tt = 0; tt < TPH; tt++) {
        const int t = half * TPH + tt;
        __syncthreads();   // all threads done with buf0/buf1 (GEMM2 of prev tree)

        // ---- issue cp.async for both W K-chunks (tf32 by HW truncation) ----
#pragma unroll
        for (int c = 0; c < 2; c++) {
#pragma unroll
            for (int m = 0; m < 8; m++) {
                int idx4 = tid + m * 256;          // node*32 + kc4
                int node = idx4 >> 5;
                int kc4 = idx4 & 31;
                int srcnode = (node < NI) ? node : (NI - 1);   // clamp; sz=0 masks
                const float* src = W + ((size_t)t * NI + srcnode) * FF + c * 128 + kc4 * 4;
                uint32_t dst = sb32 + OFF_R + c * BUFB + (uint32_t)(node * WS + kc4 * 4) * 4;
                int sz = (node < NI) ? 16 : 0;     // zero-fill pad node 63
                CP_ASYNC16(dst, src, sz);
            }
            CP_COMMIT();
        }
        if (tid < 64) bias[tid] = (tid < NI) ? split_bias[t * NI + tid] : 0.0f;

        // ---- GEMM1: D1 = X @ W^T (128x64, K=256) over 2 chunks ----
        float d1[2][4][4];
#pragma unroll
        for (int mi = 0; mi < 2; mi++)
#pragma unroll
            for (int ni = 0; ni < 4; ni++)
#pragma unroll
                for (int e = 0; e < 4; e++) d1[mi][ni][e] = 0.0f;

#pragma unroll
        for (int c = 0; c < 2; c++) {
            if (c == 0) CP_WAIT1(); else CP_WAIT0();
            __syncthreads();
            const uint32_t* Wu = (const uint32_t*)(smc + OFF_R + c * BUFB);
#pragma unroll 4
            for (int ks = 0; ks < 16; ks++) {
                const int k0 = c * 128 + ks * 8;   // global k for X
                const int kw = ks * 8;             // within-chunk k for W
                uint32_t a[2][4], b[4][2];
#pragma unroll
                for (int mi = 0; mi < 2; mi++) {
                    int r0 = wr * 32 + mi * 16 + g;
                    a[mi][0] = Xu[r0 * XS + k0 + tg];
                    a[mi][1] = Xu[(r0 + 8) * XS + k0 + tg];
                    a[mi][2] = Xu[r0 * XS + k0 + tg + 4];
                    a[mi][3] = Xu[(r0 + 8) * XS + k0 + tg + 4];
                }
#pragma unroll
                for (int ni = 0; ni < 4; ni++) {
                    int n0 = wc * 32 + ni * 8 + g;
                    b[ni][0] = Wu[n0 * WS + kw + tg];
                    b[ni][1] = Wu[n0 * WS + kw + tg + 4];
                }
#pragma unroll
                for (int mi = 0; mi < 2; mi++)
#pragma unroll
                    for (int ni = 0; ni < 4; ni++) mma8(d1[mi][ni], a[mi], b[ni]);
            }
        }
        // buf0 (chunk0) is dead for every thread (sync before chunk1 compute)
        // → sigmoid can write plT (=buf0) without an extra barrier.

        // ---- sigmoid + write plT[row][node] ----
#pragma unroll
        for (int mi = 0; mi < 2; mi++) {
            int r0 = wr * 32 + mi * 16 + g;
#pragma unroll
            for (int ni = 0; ni < 4; ni++) {
                int n0 = wc * 32 + ni * 8 + 2 * tg;
#pragma unroll
                for (int e = 0; e < 4; e++) {
                    int r = r0 + (e >> 1) * 8;
                    int n = n0 + (e & 1);
                    float z = (d1[mi][ni][e] + bias[n]) * inv_temp;
                    plT[r * PLS + n] = __fdividef(1.0f, 1.0f + __expf(-z));
                }
            }
        }
        __syncthreads();

        // ---- phase 2: heap climb -> lpT (=buf1) ----
        for (int e = tid; e < NL * BM; e += 256) {
            int leaf = e & 63;
            int row = e >> 6;
            int node = leaf + NI;
            float p = 1.0f;
#pragma unroll
            for (int d = 0; d < 6; d++) {
                int parent = (node - 1) >> 1;
                float gg = plT[row * PLS + parent];
                p *= ((node & 1) == 0) ? gg : (1.0f - gg);
                node = parent;
            }
            lpT[row * LPS + leaf] = rna_tf32(p);
        }
        __syncthreads();   // plT dead → Ms into buf0

        // ---- load Ms[class][leaf] (tf32-rounded in prep) ----
#pragma unroll
        for (int m = 0; m < 8; m++) {
            int idx4 = tid + m * 256;
            int c = idx4 >> 4, l4 = (idx4 & 15) * 4;
            *(float4*)(Ms + c * MSS + l4) =
                *(const float4*)(g_MsT + ((size_t)t * CPAD + c) * NL + l4);
        }
        __syncthreads();

        // ---- GEMM2: D2 += leafP @ Ms^T (128x128, K=64) ----
#pragma unroll
        for (int ks = 0; ks < 8; ks++) {
            const int k0 = ks * 8;
            uint32_t a[2][4], b[8][2];
#pragma unroll
            for (int mi = 0; mi < 2; mi++) {
                int r0 = wr * 32 + mi * 16 + g;
                a[mi][0] = Lu[r0 * LPS + k0 + tg];
                a[mi][1] = Lu[(r0 + 8) * LPS + k0 + tg];
                a[mi][2] = Lu[r0 * LPS + k0 + tg + 4];
                a[mi][3] = Lu[(r0 + 8) * LPS + k0 + tg + 4];
            }
#pragma unroll
            for (int ni = 0; ni < 8; ni++) {
                int n0 = wc * 64 + ni * 8 + g;
                b[ni][0] = Mu[n0 * MSS + k0 + tg];
                b[ni][1] = Mu[n0 * MSS + k0 + tg + 4];
            }
#pragma unroll
            for (int mi = 0; mi < 2; mi++)
#pragma unroll
                for (int ni = 0; ni < 8; ni++) mma8(d2[mi][ni], a[mi], b[ni]);
        }
    }

    // ---- epilogue: store partials ----
#pragma unroll
    for (int mi = 0; mi < 2; mi++) {
#pragma unroll
        for (int e2 = 0; e2 < 2; e2++) {
            int row = rowBase + wr * 32 + mi * 16 + g + e2 * 8;
            float* op = g_part + (size_t)half * (BN * CC) + (size_t)row * CC;
#pragma unroll
            for (int ni = 0; ni < 8; ni++) {
                int col = wc * 64 + ni * 8 + 2 * tg;
                if (col + 1 < CC) {
                    *(float2*)(op + col) =
                        make_float2(d2[mi][ni][e2 * 2], d2[mi][ni][e2 * 2 + 1]);
                } else if (col < CC) {
                    op[col] = d2[mi][ni][e2 * 2];
                }
            }
        }
    }
}

// ---------------- reduce -----------------------------------------------------
__global__ void reduce_kernel(float* __restrict__ out) {
    int i = blockIdx.x * blockDim.x + threadIdx.x;
    if (i >= BN * CC) return;
    out[i] = g_part[i] + g_part[BN * CC + i];
}

// dummy: pads the per-call launch count to 4 so ncu -s 5 lands on main_kernel
__global__ void dummy_kernel() {}

// ---------------- launch -----------------------------------------------------
extern "C" void kernel_launch(void* const* d_in, const int* in_sizes, int n_in,
                              void* d_out, int out_size) {
    const float* x          = nullptr;   // 2097152
    const float* split_w    = nullptr;   // 516096
    const float* split_bias = nullptr;   // 2016
    const float* leaf_log   = nullptr;   // 204800
    const float* tree_w     = nullptr;   // 32
    const float* log_temp   = nullptr;   // 1
    for (int i = 0; i < n_in; i++) {
        switch (in_sizes[i]) {
            case BN * FF:      x          = (const float*)d_in[i]; break;
            case TT * NI * FF: split_w    = (const float*)d_in[i]; break;
            case TT * NI:      split_bias = (const float*)d_in[i]; break;
            case TT * NL * CC: leaf_log   = (const float*)d_in[i]; break;
            case TT:           tree_w     = (const float*)d_in[i]; break;
            case 1:            log_temp   = (const float*)d_in[i]; break;
            default: break;
        }
    }
    if (!x)          x          = (const float*)d_in[0];
    if (!split_w)    split_w    = (const float*)d_in[1];
    if (!split_bias) split_bias = (const float*)d_in[2];
    if (!leaf_log)   leaf_log   = (const float*)d_in[3];
    if (!tree_w)     tree_w     = (const float*)d_in[4];
    if (!log_temp)   log_temp   = (const float*)d_in[5];
    float* out = (float*)d_out;

    prep_kernel<<<TT * NL, CPAD>>>(leaf_log, tree_w, log_temp);

    cudaFuncSetAttribute(main_kernel,
                         cudaFuncAttributeMaxDynamicSharedMemorySize, SMEM_BYTES);
    dim3 grid(BN / BM, NHALF);
    main_kernel<<<grid, 256, SMEM_BYTES>>>(x, split_w, split_bias);

    reduce_kernel<<<(BN * CC + 255) / 256, 256>>>(out);
    dummy_kernel<<<1, 32>>>();
}

// round 11
// speedup vs baseline: 3.0135x; 1.0206x over previous
#include <cuda_runtime.h>
#include <cuda_bf16.h>
#include <math.h>
#include <stdint.h>

// Problem constants  (B,F,T,C = 8192, 256, 32, 100)
#define BN 8192
#define FF 256
#define TT 32
#define NI 63
#define NL 64
#define CC 100
#define CPAD 128

#define BM 128            // batch rows per CTA
#define NHALF 2
#define TPH (TT / NHALF)  // 16 trees per CTA

// bf16 smem strides
#define XSB 264           // X row stride in bf16 (528 B; bank step 132≡4 mod 32)
#define WSB 264           // W node stride in bf16
#define LPB 72            // lpT row stride in bf16 (144 B; bank step 36≡4)
#define MSB 72            // Ms class stride in bf16
#define PLS 65            // plT row stride in fp32 (scalar access)

// smem byte offsets
#define OFF_X    0                      // 128*528          = 67584
#define OFF_W0   67584                  // 64*528           = 33792
#define OFF_W1   101376
#define OFF_MS0  135168                 // 128*144          = 18432
#define OFF_MS1  153600
#define OFF_PL   172032                 // 128*65*4         = 33280
#define OFF_LP   205312                 // 128*144          = 18432
#define OFF_BIAS 223744                 // 32*64*4          = 8192
#define SMEM_BYTES 231936               // <= 232448 (227 KB)

#define W_CP_CHUNKS  2112               // 33792/16
#define MS_CP_CHUNKS 1152               // 18432/16

__device__ __forceinline__ uint32_t smem_u32(const void* p) {
    uint32_t a;
    asm("{ .reg .u64 t; cvta.to.shared.u64 t, %1; cvt.u32.u64 %0, t; }" : "=r"(a) : "l"(p));
    return a;
}
#define CP_ASYNC16(dst, src) \
    asm volatile("cp.async.cg.shared.global [%0], [%1], 16;" :: "r"(dst), "l"(src) : "memory")
#define CP_COMMIT() asm volatile("cp.async.commit_group;" ::: "memory")
#define CP_WAIT0()  asm volatile("cp.async.wait_group 0;" ::: "memory")

__device__ __forceinline__ uint32_t pack_bf16x2(float hi, float lo) {
    uint32_t r;
    asm("cvt.rn.bf16x2.f32 %0, %1, %2;" : "=r"(r) : "f"(hi), "f"(lo));
    return r;
}

__device__ __forceinline__ void mma16(float d[4], const uint32_t a[4], const uint32_t b[2]) {
    asm volatile(
        "mma.sync.aligned.m16n8k16.row.col.f32.bf16.bf16.f32 "
        "{%0,%1,%2,%3}, {%4,%5,%6,%7}, {%8,%9}, {%0,%1,%2,%3};"
        : "+f"(d[0]), "+f"(d[1]), "+f"(d[2]), "+f"(d[3])
        : "r"(a[0]), "r"(a[1]), "r"(a[2]), "r"(a[3]), "r"(b[0]), "r"(b[1]));
}

// ---------------- scratch ----------------------------------------------------
__device__ float g_scalars[4];
__device__ uint4 g_Wbf[TT * W_CP_CHUNKS];     // [t][node(64)][k(264)] bf16, node63/k>=256 zero
__device__ uint4 g_Msbf[TT * MS_CP_CHUNKS];   // [t][class(128)][leaf stride 72] bf16
__device__ float g_part[NHALF * BN * CC];

// ---------------- prep1: Ms (bf16) + tree softmax + inv_temp ----------------
__global__ void prep1_kernel(const float* __restrict__ leaf_logits,
                             const float* __restrict__ tw,
                             const float* __restrict__ log_temp) {
    __shared__ float sv[CPAD];
    __shared__ float s_mx, s_inv, s_w, s_it;
    int blk = blockIdx.x;           // t*64 + l
    int t = blk >> 6, l = blk & 63;
    int c = threadIdx.x;            // 0..127
    if (c == 0) {
        float temp = expf(log_temp[0]);
        temp = fminf(fmaxf(temp, 0.1f), 5.0f);
        float it = 1.0f / temp;
        s_it = it;
        if (blk == 0) g_scalars[0] = it;
        float mx = -INFINITY;
        for (int i = 0; i < TT; i++) mx = fmaxf(mx, tw[i]);
        float s = 0.0f;
        for (int i = 0; i < TT; i++) s += expf(tw[i] - mx);
        s_w = expf(tw[t] - mx) / s;
    }
    __syncthreads();
    float v = (c < CC) ? leaf_logits[(size_t)blk * CC + c] * s_it : -INFINITY;
    sv[c] = v;
    __syncthreads();
    if (c == 0) {
        float mx = -INFINITY;
        for (int i = 0; i < CC; i++) mx = fmaxf(mx, sv[i]);
        float s = 0.0f;
        for (int i = 0; i < CC; i++) s += expf(sv[i] - mx);
        s_mx = mx; s_inv = 1.0f / s;
    }
    __syncthreads();
    float r = (c < CC) ? s_w * expf(v - s_mx) * s_inv : 0.0f;
    __nv_bfloat16* Mb = (__nv_bfloat16*)g_Msbf;
    Mb[((size_t)t * CPAD + c) * MSB + l] = __float2bfloat16(r);
}

// ---------------- prep2: W -> bf16 (node 63 / k>=256 zero) ------------------
__global__ void prep2_kernel(const float* __restrict__ W) {
    int t = blockIdx.x;
    __nv_bfloat16* Wb = (__nv_bfloat16*)g_Wbf;
    for (int i = threadIdx.x; i < NL * WSB; i += blockDim.x) {
        int node = i / WSB;
        int k = i - node * WSB;
        float v = (node < NI && k < FF) ? W[((size_t)t * NI + node) * FF + k] : 0.0f;
        Wb[(size_t)t * NL * WSB + i] = __float2bfloat16(v);
    }
}

// ---------------- main kernel ------------------------------------------------
__global__ __launch_bounds__(256, 1)
void main_kernel(const float* __restrict__ x,
                 const float* __restrict__ split_bias) {
    extern __shared__ float sm[];
    char* smc = (char*)sm;
    const uint32_t sb32 = smem_u32(sm);
    float* plT  = (float*)(smc + OFF_PL);
    char*  lpB  = smc + OFF_LP;
    float* sbias = (float*)(smc + OFF_BIAS);
    const uint32_t* Xu = (const uint32_t*)(smc + OFF_X);
    const uint32_t* Lu = (const uint32_t*)(smc + OFF_LP);

    const int tid = threadIdx.x;
    const int wid = tid >> 5;
    const int lane = tid & 31;
    const int g = lane >> 2;
    const int tg = lane & 3;
    const int wr = wid & 3;
    const int wc = wid >> 2;
    const int rowBase = blockIdx.x * BM;
    const int half = blockIdx.y;
    const float inv_temp = g_scalars[0];
    const int t0 = half * TPH;

    // ---- prologue: prefetch W(0)+Ms(0) ----
    {
        const uint4* wsrc = g_Wbf + (size_t)t0 * W_CP_CHUNKS;
        const uint4* msrc = g_Msbf + (size_t)t0 * MS_CP_CHUNKS;
#pragma unroll
        for (int m = 0; m < 9; m++) {
            int idx = tid + m * 256;
            if (idx < W_CP_CHUNKS) CP_ASYNC16(sb32 + OFF_W0 + idx * 16, wsrc + idx);
        }
#pragma unroll
        for (int m = 0; m < 5; m++) {
            int idx = tid + m * 256;
            if (idx < MS_CP_CHUNKS) CP_ASYNC16(sb32 + OFF_MS0 + idx * 16, msrc + idx);
        }
        CP_COMMIT();
    }

    // ---- stage X tile fp32 -> bf16 ----
#pragma unroll
    for (int m = 0; m < 32; m++) {
        int idx4 = tid + m * 256;          // row*64 + kc
        int row = idx4 >> 6, kc = idx4 & 63;
        float4 v = *(const float4*)(x + (size_t)(rowBase + row) * FF + kc * 4);
        uint32_t r0 = pack_bf16x2(v.y, v.x);
        uint32_t r1 = pack_bf16x2(v.w, v.z);
        *(uint2*)(smc + OFF_X + row * (XSB * 2) + kc * 8) = make_uint2(r0, r1);
    }
    // ---- stage all 32 trees' bias ----
#pragma unroll
    for (int m = 0; m < 8; m++) {
        int i = tid + m * 256;             // t*64 + node
        int tb = i >> 6, node = i & 63;
        sbias[i] = (node < NI) ? split_bias[tb * NI + node] : 0.0f;
    }

    float d2[2][8][4];
#pragma unroll
    for (int mi = 0; mi < 2; mi++)
#pragma unroll
        for (int ni = 0; ni < 8; ni++)
#pragma unroll
            for (int e = 0; e < 4; e++) d2[mi][ni][e] = 0.0f;

    for (int tt = 0; tt < TPH; tt++) {
        const int t = t0 + tt;
        const uint32_t offW  = (tt & 1) ? OFF_W1 : OFF_W0;
        const uint32_t offMs = (tt & 1) ? OFF_MS1 : OFF_MS0;
        const float* biasp = sbias + t * 64;

        CP_WAIT0();          // W(t)+Ms(t) landed
        __syncthreads();

        // ---- prefetch W(t+1)+Ms(t+1) into the other buffers ----
        if (tt + 1 < TPH) {
            const uint32_t oW  = (tt & 1) ? OFF_W0 : OFF_W1;
            const uint32_t oM  = (tt & 1) ? OFF_MS0 : OFF_MS1;
            const uint4* wsrc = g_Wbf + (size_t)(t + 1) * W_CP_CHUNKS;
            const uint4* msrc = g_Msbf + (size_t)(t + 1) * MS_CP_CHUNKS;
#pragma unroll
            for (int m = 0; m < 9; m++) {
                int idx = tid + m * 256;
                if (idx < W_CP_CHUNKS) CP_ASYNC16(sb32 + oW + idx * 16, wsrc + idx);
            }
#pragma unroll
            for (int m = 0; m < 5; m++) {
                int idx = tid + m * 256;
                if (idx < MS_CP_CHUNKS) CP_ASYNC16(sb32 + oM + idx * 16, msrc + idx);
            }
            CP_COMMIT();
        }

        // ---- GEMM1: D1 = X @ W^T (128x64, K=256), bf16 m16n8k16 ----
        const uint32_t* Wu = (const uint32_t*)(smc + offW);
        float d1[2][4][4];
#pragma unroll
        for (int mi = 0; mi < 2; mi++)
#pragma unroll
            for (int ni = 0; ni < 4; ni++)
#pragma unroll
                for (int e = 0; e < 4; e++) d1[mi][ni][e] = 0.0f;

#pragma unroll 4
        for (int ks = 0; ks < 16; ks++) {
            const int kb = ks * 8;         // uint32 offset (16 bf16 per ks)
            uint32_t a[2][4], b[4][2];
#pragma unroll
            for (int mi = 0; mi < 2; mi++) {
                int r0 = wr * 32 + mi * 16 + g;
                a[mi][0] = Xu[r0 * 132 + kb + tg];
                a[mi][1] = Xu[(r0 + 8) * 132 + kb + tg];
                a[mi][2] = Xu[r0 * 132 + kb + tg + 4];
                a[mi][3] = Xu[(r0 + 8) * 132 + kb + tg + 4];
            }
#pragma unroll
            for (int ni = 0; ni < 4; ni++) {
                int n0 = wc * 32 + ni * 8 + g;
                b[ni][0] = Wu[n0 * 132 + kb + tg];
                b[ni][1] = Wu[n0 * 132 + kb + tg + 4];
            }
#pragma unroll
            for (int mi = 0; mi < 2; mi++)
#pragma unroll
                for (int ni = 0; ni < 4; ni++) mma16(d1[mi][ni], a[mi], b[ni]);
        }

        // ---- sigmoid -> plT[row][node] ----
#pragma unroll
        for (int mi = 0; mi < 2; mi++) {
            int r0 = wr * 32 + mi * 16 + g;
#pragma unroll
            for (int ni = 0; ni < 4; ni++) {
                int n0 = wc * 32 + ni * 8 + 2 * tg;
#pragma unroll
                for (int e = 0; e < 4; e++) {
                    int r = r0 + (e >> 1) * 8;
                    int n = n0 + (e & 1);
                    float z = (d1[mi][ni][e] + biasp[n]) * inv_temp;
                    plT[r * PLS + n] = __fdividef(1.0f, 1.0f + __expf(-z));
                }
            }
        }
        __syncthreads();

        // ---- heap climb, leaf pairs -> lpT bf16 ----
        for (int e = tid; e < (NL / 2) * BM; e += 256) {   // 16 iters
            int j = e & 31;                 // leaf pair index
            int row = e >> 5;
            const float* pl = plT + row * PLS;
            float pp = 1.0f;
#pragma unroll
            for (int d = 0; d < 5; d++) {
                int sub = j >> (4 - d);
                float gg = pl[((1 << d) - 1) + (j >> (5 - d))];
                pp *= (sub & 1) ? gg : (1.0f - gg);
            }
            float g6 = pl[31 + j];
            uint32_t pk = pack_bf16x2(pp * g6, pp * (1.0f - g6));  // hi=leaf 2j+1
            *(uint32_t*)(lpB + row * 144 + j * 4) = pk;
        }
        __syncthreads();

        // ---- GEMM2: D2 += leafP @ Ms^T (128x128, K=64), bf16 ----
        const uint32_t* Mu = (const uint32_t*)(smc + offMs);
#pragma unroll
        for (int ks = 0; ks < 4; ks++) {
            const int kb = ks * 8;
            uint32_t a[2][4], b[8][2];
#pragma unroll
            for (int mi = 0; mi < 2; mi++) {
                int r0 = wr * 32 + mi * 16 + g;
                a[mi][0] = Lu[r0 * 36 + kb + tg];
                a[mi][1] = Lu[(r0 + 8) * 36 + kb + tg];
                a[mi][2] = Lu[r0 * 36 + kb + tg + 4];
                a[mi][3] = Lu[(r0 + 8) * 36 + kb + tg + 4];
            }
#pragma unroll
            for (int ni = 0; ni < 8; ni++) {
                int n0 = wc * 64 + ni * 8 + g;
                b[ni][0] = Mu[n0 * 36 + kb + tg];
                b[ni][1] = Mu[n0 * 36 + kb + tg + 4];
            }
#pragma unroll
            for (int mi = 0; mi < 2; mi++)
#pragma unroll
                for (int ni = 0; ni < 8; ni++) mma16(d2[mi][ni], a[mi], b[ni]);
        }
    }

    // ---- epilogue: store partials ----
#pragma unroll
    for (int mi = 0; mi < 2; mi++) {
#pragma unroll
        for (int e2 = 0; e2 < 2; e2++) {
            int row = rowBase + wr * 32 + mi * 16 + g + e2 * 8;
            float* op = g_part + (size_t)half * (BN * CC) + (size_t)row * CC;
#pragma unroll
            for (int ni = 0; ni < 8; ni++) {
                int col = wc * 64 + ni * 8 + 2 * tg;
                if (col + 1 < CC) {
                    *(float2*)(op + col) =
                        make_float2(d2[mi][ni][e2 * 2], d2[mi][ni][e2 * 2 + 1]);
                } else if (col < CC) {
                    op[col] = d2[mi][ni][e2 * 2];
                }
            }
        }
    }
}

// ---------------- reduce -----------------------------------------------------
__global__ void reduce_kernel(float* __restrict__ out) {
    int i = blockIdx.x * blockDim.x + threadIdx.x;
    if (i >= BN * CC) return;
    out[i] = g_part[i] + g_part[BN * CC + i];
}

// ---------------- launch -----------------------------------------------------
extern "C" void kernel_launch(void* const* d_in, const int* in_sizes, int n_in,
                              void* d_out, int out_size) {
    const float* x          = nullptr;   // 2097152
    const float* split_w    = nullptr;   // 516096
    const float* split_bias = nullptr;   // 2016
    const float* leaf_log   = nullptr;   // 204800
    const float* tree_w     = nullptr;   // 32
    const float* log_temp   = nullptr;   // 1
    for (int i = 0; i < n_in; i++) {
        switch (in_sizes[i]) {
            case BN * FF:      x          = (const float*)d_in[i]; break;
            case TT * NI * FF: split_w    = (const float*)d_in[i]; break;
            case TT * NI:      split_bias = (const float*)d_in[i]; break;
            case TT * NL * CC: leaf_log   = (const float*)d_in[i]; break;
            case TT:           tree_w     = (const float*)d_in[i]; break;
            case 1:            log_temp   = (const float*)d_in[i]; break;
            default: break;
        }
    }
    if (!x)          x          = (const float*)d_in[0];
    if (!split_w)    split_w    = (const float*)d_in[1];
    if (!split_bias) split_bias = (const float*)d_in[2];
    if (!leaf_log)   leaf_log   = (const float*)d_in[3];
    if (!tree_w)     tree_w     = (const float*)d_in[4];
    if (!log_temp)   log_temp   = (const float*)d_in[5];
    float* out = (float*)d_out;

    prep1_kernel<<<TT * NL, CPAD>>>(leaf_log, tree_w, log_temp);
    prep2_kernel<<<TT, 256>>>(split_w);

    cudaFuncSetAttribute(main_kernel,
                         cudaFuncAttributeMaxDynamicSharedMemorySize, SMEM_BYTES);
    dim3 grid(BN / BM, NHALF);
    main_kernel<<<grid, 256, SMEM_BYTES>>>(x, split_bias);

    reduce_kernel<<<(BN * CC + 255) / 256, 256>>>(out);
}

// round 13
// speedup vs baseline: 4.5526x; 1.5108x over previous
#include <cuda_runtime.h>
#include <cuda_bf16.h>
#include <math.h>
#include <stdint.h>

// Problem constants  (B,F,T,C = 8192, 256, 32, 100)
#define BN 8192
#define FF 256
#define TT 32
#define NI 63
#define NL 64
#define CC 100
#define CPAD 112          // padded class dim (14 x 8)

#define BM 128            // batch rows per CTA
#define NHALF 2
#define TPH (TT / NHALF)  // 16 trees per CTA

// bf16 smem strides
#define XSB 264           // X row stride in bf16
#define WSB 264           // W node stride in bf16
#define LPB 72            // lpT row stride in bf16
#define MSB 72            // Ms class stride in bf16
#define PLS 65            // plT row stride in fp32

// smem byte offsets
#define OFF_X    0                      // 128*528 = 67584
#define OFF_W0   67584                  // 64*528  = 33792
#define OFF_W1   101376
#define OFF_MS0  135168                 // 112*144 = 16128
#define OFF_MS1  151296
#define OFF_PL   167424                 // 128*65*4 = 33280
#define OFF_LP   200704                 // 128*144  = 18432
#define OFF_BIAS 219136                 // 32*64*4  = 8192
#define SMEM_BYTES 227328

#define W_CP_CHUNKS  2112               // 33792/16
#define MS_CP_CHUNKS 1008               // 16128/16

__device__ __forceinline__ uint32_t smem_u32(const void* p) {
    uint32_t a;
    asm("{ .reg .u64 t; cvta.to.shared.u64 t, %1; cvt.u32.u64 %0, t; }" : "=r"(a) : "l"(p));
    return a;
}
#define CP_ASYNC16(dst, src) \
    asm volatile("cp.async.cg.shared.global [%0], [%1], 16;" :: "r"(dst), "l"(src) : "memory")
#define CP_COMMIT() asm volatile("cp.async.commit_group;" ::: "memory")
#define CP_WAIT1()  asm volatile("cp.async.wait_group 1;" ::: "memory")
#define CP_WAIT0()  asm volatile("cp.async.wait_group 0;" ::: "memory")

__device__ __forceinline__ uint32_t pack_bf16x2(float hi, float lo) {
    uint32_t r;
    asm("cvt.rn.bf16x2.f32 %0, %1, %2;" : "=r"(r) : "f"(hi), "f"(lo));
    return r;
}

__device__ __forceinline__ void mma16(float d[4], const uint32_t a[4], const uint32_t b[2]) {
    asm volatile(
        "mma.sync.aligned.m16n8k16.row.col.f32.bf16.bf16.f32 "
        "{%0,%1,%2,%3}, {%4,%5,%6,%7}, {%8,%9}, {%0,%1,%2,%3};"
        : "+f"(d[0]), "+f"(d[1]), "+f"(d[2]), "+f"(d[3])
        : "r"(a[0]), "r"(a[1]), "r"(a[2]), "r"(a[3]), "r"(b[0]), "r"(b[1]));
}

// ---------------- scratch ----------------------------------------------------
__device__ float g_scalars[4];
__device__ uint4 g_Wbf[TT * W_CP_CHUNKS];     // [t][node(64)][k stride 264] bf16
__device__ uint4 g_Msbf[TT * MS_CP_CHUNKS];   // [t][class(112)][leaf stride 72] bf16
__device__ float g_part[NHALF * BN * CC];

// ---------------- prep1: Ms (bf16) + tree softmax + inv_temp ----------------
__global__ void prep1_kernel(const float* __restrict__ leaf_logits,
                             const float* __restrict__ tw,
                             const float* __restrict__ log_temp) {
    __shared__ float sv[128];
    __shared__ float s_mx, s_inv, s_w, s_it;
    int blk = blockIdx.x;           // t*64 + l
    int t = blk >> 6, l = blk & 63;
    int c = threadIdx.x;            // 0..127
    if (c == 0) {
        float temp = expf(log_temp[0]);
        temp = fminf(fmaxf(temp, 0.1f), 5.0f);
        float it = 1.0f / temp;
        s_it = it;
        if (blk == 0) g_scalars[0] = it;
        float mx = -INFINITY;
        for (int i = 0; i < TT; i++) mx = fmaxf(mx, tw[i]);
        float s = 0.0f;
        for (int i = 0; i < TT; i++) s += expf(tw[i] - mx);
        s_w = expf(tw[t] - mx) / s;
    }
    __syncthreads();
    float v = (c < CC) ? leaf_logits[(size_t)blk * CC + c] * s_it : -INFINITY;
    sv[c] = v;
    __syncthreads();
    if (c == 0) {
        float mx = -INFINITY;
        for (int i = 0; i < CC; i++) mx = fmaxf(mx, sv[i]);
        float s = 0.0f;
        for (int i = 0; i < CC; i++) s += expf(sv[i] - mx);
        s_mx = mx; s_inv = 1.0f / s;
    }
    __syncthreads();
    if (c < CPAD) {
        float r = (c < CC) ? s_w * expf(v - s_mx) * s_inv : 0.0f;
        __nv_bfloat16* Mb = (__nv_bfloat16*)g_Msbf;
        Mb[((size_t)t * CPAD + c) * MSB + l] = __float2bfloat16(r);
    }
}

// ---------------- prep2: W -> bf16 (node 63 / k>=256 zero) ------------------
__global__ void prep2_kernel(const float* __restrict__ W) {
    int t = blockIdx.x;
    __nv_bfloat16* Wb = (__nv_bfloat16*)g_Wbf;
    for (int i = threadIdx.x; i < NL * WSB; i += blockDim.x) {
        int node = i / WSB;
        int k = i - node * WSB;
        float v = (node < NI && k < FF) ? W[((size_t)t * NI + node) * FF + k] : 0.0f;
        Wb[(size_t)t * NL * WSB + i] = __float2bfloat16(v);
    }
}

// ---------------- prefetch helpers ------------------------------------------
__device__ __forceinline__ void prefetch_W(uint32_t sb32, int tid, int t, uint32_t slotOff) {
    const uint4* src = g_Wbf + (size_t)t * W_CP_CHUNKS;
#pragma unroll
    for (int m = 0; m < 9; m++) {
        int idx = tid + m * 256;
        if (idx < W_CP_CHUNKS) CP_ASYNC16(sb32 + slotOff + idx * 16, src + idx);
    }
    CP_COMMIT();
}
__device__ __forceinline__ void prefetch_Ms(uint32_t sb32, int tid, int t, uint32_t slotOff) {
    const uint4* src = g_Msbf + (size_t)t * MS_CP_CHUNKS;
#pragma unroll
    for (int m = 0; m < 4; m++) {
        int idx = tid + m * 256;
        if (idx < MS_CP_CHUNKS) CP_ASYNC16(sb32 + slotOff + idx * 16, src + idx);
    }
    CP_COMMIT();
}

// ---------------- main kernel ------------------------------------------------
__global__ __launch_bounds__(256, 1)
void main_kernel(const float* __restrict__ x,
                 const float* __restrict__ split_bias) {
    extern __shared__ float sm[];
    char* smc = (char*)sm;
    const uint32_t sb32 = smem_u32(sm);
    float* plT   = (float*)(smc + OFF_PL);
    char*  lpB   = smc + OFF_LP;
    float* sbias = (float*)(smc + OFF_BIAS);
    const uint32_t* Xu = (const uint32_t*)(smc + OFF_X);
    const uint32_t* Lu = (const uint32_t*)(smc + OFF_LP);

    const int tid = threadIdx.x;
    const int wid = tid >> 5;
    const int lane = tid & 31;
    const int g = lane >> 2;
    const int tg = lane & 3;
    const int wr = wid & 3;
    const int wc = wid >> 2;
    const int rowBase = blockIdx.x * BM;
    const int half = blockIdx.y;
    const float inv_temp = g_scalars[0];
    const int t0 = half * TPH;

    // ---- prologue: prefetch group A = W(0)+Ms(0); group B = W(1) ----
    {
        const uint4* wsrc = g_Wbf + (size_t)t0 * W_CP_CHUNKS;
        const uint4* msrc = g_Msbf + (size_t)t0 * MS_CP_CHUNKS;
#pragma unroll
        for (int m = 0; m < 9; m++) {
            int idx = tid + m * 256;
            if (idx < W_CP_CHUNKS) CP_ASYNC16(sb32 + OFF_W0 + idx * 16, wsrc + idx);
        }
#pragma unroll
        for (int m = 0; m < 4; m++) {
            int idx = tid + m * 256;
            if (idx < MS_CP_CHUNKS) CP_ASYNC16(sb32 + OFF_MS0 + idx * 16, msrc + idx);
        }
        CP_COMMIT();
        prefetch_W(sb32, tid, t0 + 1, OFF_W1);
    }

    // ---- stage X tile fp32 -> bf16 ----
#pragma unroll
    for (int m = 0; m < 32; m++) {
        int idx4 = tid + m * 256;          // row*64 + kc
        int row = idx4 >> 6, kc = idx4 & 63;
        float4 v = *(const float4*)(x + (size_t)(rowBase + row) * FF + kc * 4);
        uint32_t r0 = pack_bf16x2(v.y, v.x);
        uint32_t r1 = pack_bf16x2(v.w, v.z);
        *(uint2*)(smc + OFF_X + row * (XSB * 2) + kc * 8) = make_uint2(r0, r1);
    }
    // ---- stage all trees' bias ----
#pragma unroll
    for (int m = 0; m < 8; m++) {
        int i = tid + m * 256;
        int tb = i >> 6, node = i & 63;
        sbias[i] = (node < NI) ? split_bias[tb * NI + node] : 0.0f;
    }

    CP_WAIT1();            // W(0)+Ms(0) landed (W(1) may be in flight)
    __syncthreads();

    float d2[2][7][4];
#pragma unroll
    for (int mi = 0; mi < 2; mi++)
#pragma unroll
        for (int ni = 0; ni < 7; ni++)
#pragma unroll
            for (int e = 0; e < 4; e++) d2[mi][ni][e] = 0.0f;

    float d1[2][4][4];

    // ---- GEMM1 for a given W slot ----
    auto gemm1 = [&](uint32_t offW) {
        const uint32_t* Wu = (const uint32_t*)(smc + offW);
#pragma unroll
        for (int mi = 0; mi < 2; mi++)
#pragma unroll
            for (int ni = 0; ni < 4; ni++)
#pragma unroll
                for (int e = 0; e < 4; e++) d1[mi][ni][e] = 0.0f;
#pragma unroll 4
        for (int ks = 0; ks < 16; ks++) {
            const int kb = ks * 8;
            uint32_t a[2][4], b[4][2];
#pragma unroll
            for (int mi = 0; mi < 2; mi++) {
                int r0 = wr * 32 + mi * 16 + g;
                a[mi][0] = Xu[r0 * 132 + kb + tg];
                a[mi][1] = Xu[(r0 + 8) * 132 + kb + tg];
                a[mi][2] = Xu[r0 * 132 + kb + tg + 4];
                a[mi][3] = Xu[(r0 + 8) * 132 + kb + tg + 4];
            }
#pragma unroll
            for (int ni = 0; ni < 4; ni++) {
                int n0 = wc * 32 + ni * 8 + g;
                b[ni][0] = Wu[n0 * 132 + kb + tg];
                b[ni][1] = Wu[n0 * 132 + kb + tg + 4];
            }
#pragma unroll
            for (int mi = 0; mi < 2; mi++)
#pragma unroll
                for (int ni = 0; ni < 4; ni++) mma16(d1[mi][ni], a[mi], b[ni]);
        }
    };

    gemm1(OFF_W0);          // GEMM1(t0)

    for (int tt = 0; tt < TPH; tt++) {
        const int t = t0 + tt;
        const float* biasp = sbias + t * 64;

        // ---- sigmoid(t) from d1 -> plT ----
#pragma unroll
        for (int mi = 0; mi < 2; mi++) {
            int r0 = wr * 32 + mi * 16 + g;
#pragma unroll
            for (int ni = 0; ni < 4; ni++) {
                int n0 = wc * 32 + ni * 8 + 2 * tg;
#pragma unroll
                for (int e = 0; e < 4; e++) {
                    int r = r0 + (e >> 1) * 8;
                    int n = n0 + (e & 1);
                    float z = (d1[mi][ni][e] + biasp[n]) * inv_temp;
                    plT[r * PLS + n] = __fdividef(1.0f, 1.0f + __expf(-z));
                }
            }
        }
        __syncthreads();    // sync1: plT complete; GEMM2(t-1) done by all

        // ---- prefetch Ms(t+1) into slot (tt+1)&1 ----
        if (tt + 1 < TPH)
            prefetch_Ms(sb32, tid, t + 1, ((tt + 1) & 1) ? OFF_MS1 : OFF_MS0);

        // ---- heap climb (t): plT -> lpT bf16 ----
        for (int e = tid; e < (NL / 2) * BM; e += 256) {
            int j = e & 31;
            int row = e >> 5;
            const float* pl = plT + row * PLS;
            float pp = 1.0f;
#pragma unroll
            for (int d = 0; d < 5; d++) {
                int sub = j >> (4 - d);
                float gg = pl[((1 << d) - 1) + (j >> (5 - d))];
                pp *= (sub & 1) ? gg : (1.0f - gg);
            }
            float g6 = pl[31 + j];
            uint32_t pk = pack_bf16x2(pp * g6, pp * (1.0f - g6));
            *(uint32_t*)(lpB + row * 144 + j * 4) = pk;
        }

        if (tt == TPH - 1) CP_WAIT0(); else CP_WAIT1();
        __syncthreads();    // sync2: lpT complete; W(t+1), Ms(t) visible

        // ---- GEMM1(t+1) ----
        if (tt + 1 < TPH) gemm1(((tt + 1) & 1) ? OFF_W1 : OFF_W0);

        // ---- GEMM2(t): D2 += leafP @ Ms^T (128x112, K=64) ----
        const uint32_t* Mu = (const uint32_t*)(smc + ((tt & 1) ? OFF_MS1 : OFF_MS0));
#pragma unroll
        for (int ks = 0; ks < 4; ks++) {
            const int kb = ks * 8;
            uint32_t a[2][4], b[7][2];
#pragma unroll
            for (int mi = 0; mi < 2; mi++) {
                int r0 = wr * 32 + mi * 16 + g;
                a[mi][0] = Lu[r0 * 36 + kb + tg];
                a[mi][1] = Lu[(r0 + 8) * 36 + kb + tg];
                a[mi][2] = Lu[r0 * 36 + kb + tg + 4];
                a[mi][3] = Lu[(r0 + 8) * 36 + kb + tg + 4];
            }
#pragma unroll
            for (int ni = 0; ni < 7; ni++) {
                int n0 = wc * 56 + ni * 8 + g;
                b[ni][0] = Mu[n0 * 36 + kb + tg];
                b[ni][1] = Mu[n0 * 36 + kb + tg + 4];
            }
#pragma unroll
            for (int mi = 0; mi < 2; mi++)
#pragma unroll
                for (int ni = 0; ni < 7; ni++) mma16(d2[mi][ni], a[mi], b[ni]);
        }

        // ---- prefetch W(t+2) into slot tt&1 (the slot gemm1(t+2) reads) ----
        if (tt + 2 < TPH)
            prefetch_W(sb32, tid, t + 2, (tt & 1) ? OFF_W1 : OFF_W0);
    }

    // ---- epilogue: store partials ----
#pragma unroll
    for (int mi = 0; mi < 2; mi++) {
#pragma unroll
        for (int e2 = 0; e2 < 2; e2++) {
            int row = rowBase + wr * 32 + mi * 16 + g + e2 * 8;
            float* op = g_part + (size_t)half * (BN * CC) + (size_t)row * CC;
#pragma unroll
            for (int ni = 0; ni < 7; ni++) {
                int col = wc * 56 + ni * 8 + 2 * tg;
                if (col + 1 < CC) {
                    *(float2*)(op + col) =
                        make_float2(d2[mi][ni][e2 * 2], d2[mi][ni][e2 * 2 + 1]);
                } else if (col < CC) {
                    op[col] = d2[mi][ni][e2 * 2];
                }
            }
        }
    }
}

// ---------------- reduce -----------------------------------------------------
__global__ void reduce_kernel(float* __restrict__ out) {
    int i = blockIdx.x * blockDim.x + threadIdx.x;
    if (i >= BN * CC) return;
    out[i] = g_part[i] + g_part[BN * CC + i];
}

// ---------------- launch -----------------------------------------------------
extern "C" void kernel_launch(void* const* d_in, const int* in_sizes, int n_in,
                              void* d_out, int out_size) {
    const float* x          = nullptr;   // 2097152
    const float* split_w    = nullptr;   // 516096
    const float* split_bias = nullptr;   // 2016
    const float* leaf_log   = nullptr;   // 204800
    const float* tree_w     = nullptr;   // 32
    const float* log_temp   = nullptr;   // 1
    for (int i = 0; i < n_in; i++) {
        switch (in_sizes[i]) {
            case BN * FF:      x          = (const float*)d_in[i]; break;
            case TT * NI * FF: split_w    = (const float*)d_in[i]; break;
            case TT * NI:      split_bias = (const float*)d_in[i]; break;
            case TT * NL * CC: leaf_log   = (const float*)d_in[i]; break;
            case TT:           tree_w     = (const float*)d_in[i]; break;
            case 1:            log_temp   = (const float*)d_in[i]; break;
            default: break;
        }
    }
    if (!x)          x          = (const float*)d_in[0];
    if (!split_w)    split_w    = (const float*)d_in[1];
    if (!split_bias) split_bias = (const float*)d_in[2];
    if (!leaf_log)   leaf_log   = (const float*)d_in[3];
    if (!tree_w)     tree_w     = (const float*)d_in[4];
    if (!log_temp)   log_temp   = (const float*)d_in[5];
    float* out = (float*)d_out;

    prep1_kernel<<<TT * NL, 128>>>(leaf_log, tree_w, log_temp);
    prep2_kernel<<<TT, 256>>>(split_w);

    cudaFuncSetAttribute(main_kernel,
                         cudaFuncAttributeMaxDynamicSharedMemorySize, SMEM_BYTES);
    dim3 grid(BN / BM, NHALF);
    main_kernel<<<grid, 256, SMEM_BYTES>>>(x, split_bias);

    reduce_kernel<<<(BN * CC + 255) / 256, 256>>>(out);
}

// round 14
// speedup vs baseline: 4.6928x; 1.0308x over previous
#include <cuda_runtime.h>
#include <cuda_bf16.h>
#include <math.h>
#include <stdint.h>

// Problem constants  (B,F,T,C = 8192, 256, 32, 100)
#define BN 8192
#define FF 256
#define TT 32
#define NI 63
#define NL 64
#define CC 100
#define CPAD 104          // padded class dim (13 x 8)

#define BM 128            // batch rows per CTA
#define NHALF 2
#define TPH (TT / NHALF)  // 16 trees per CTA

// bf16 smem strides
#define XSB 264           // X row stride in bf16
#define WSB 264           // W node stride in bf16
#define MSB 72            // Ms class stride in bf16
#define PLS 65            // plT row stride in fp32

// smem byte offsets
#define OFF_X    0                      // 128*528 = 67584
#define OFF_W0   67584                  // 64*528  = 33792
#define OFF_W1   101376
#define OFF_MS0  135168                 // 104*144 = 14976
#define OFF_MS1  150144
#define OFF_PL   165120                 // 128*65*4 = 33280
#define OFF_LP   198400                 // 128*144  = 18432
#define OFF_BIAS 216832                 // 32*64*4  = 8192
#define SMEM_BYTES 225024

#define W_CP_CHUNKS  2112               // 33792/16
#define MS_CP_CHUNKS 936                // 14976/16

__device__ __forceinline__ uint32_t smem_u32(const void* p) {
    uint32_t a;
    asm("{ .reg .u64 t; cvta.to.shared.u64 t, %1; cvt.u32.u64 %0, t; }" : "=r"(a) : "l"(p));
    return a;
}
#define CP_ASYNC16(dst, src) \
    asm volatile("cp.async.cg.shared.global [%0], [%1], 16;" :: "r"(dst), "l"(src) : "memory")
#define CP_COMMIT() asm volatile("cp.async.commit_group;" ::: "memory")
#define CP_WAIT1()  asm volatile("cp.async.wait_group 1;" ::: "memory")
#define CP_WAIT0()  asm volatile("cp.async.wait_group 0;" ::: "memory")

__device__ __forceinline__ uint32_t pack_bf16x2(float hi, float lo) {
    uint32_t r;
    asm("cvt.rn.bf16x2.f32 %0, %1, %2;" : "=r"(r) : "f"(hi), "f"(lo));
    return r;
}

__device__ __forceinline__ void mma16(float d[4], const uint32_t a[4], const uint32_t b[2]) {
    asm volatile(
        "mma.sync.aligned.m16n8k16.row.col.f32.bf16.bf16.f32 "
        "{%0,%1,%2,%3}, {%4,%5,%6,%7}, {%8,%9}, {%0,%1,%2,%3};"
        : "+f"(d[0]), "+f"(d[1]), "+f"(d[2]), "+f"(d[3])
        : "r"(a[0]), "r"(a[1]), "r"(a[2]), "r"(a[3]), "r"(b[0]), "r"(b[1]));
}

// ---------------- scratch ----------------------------------------------------
__device__ float g_scalars[4];
__device__ uint4 g_Wbf[TT * W_CP_CHUNKS];     // [t][node(64)][k stride 264] bf16
__device__ uint4 g_Msbf[TT * MS_CP_CHUNKS];   // [t][class(104)][leaf stride 72] bf16

// ---------------- merged prep: Ms build (blocks 0..2047) + W cvt (2048..) ---
__global__ void prep_kernel(const float* __restrict__ leaf_logits,
                            const float* __restrict__ tw,
                            const float* __restrict__ log_temp,
                            const float* __restrict__ W) {
    int blk = blockIdx.x;
    int c = threadIdx.x;               // 0..127

    if (blk >= TT * NL) {              // ---- W conversion path ----
        int t = blk - TT * NL;
        __nv_bfloat16* Wb = (__nv_bfloat16*)g_Wbf;
        for (int i = c; i < NL * WSB; i += 128) {
            int node = i / WSB;
            int k = i - node * WSB;
            float v = (node < NI && k < FF) ? W[((size_t)t * NI + node) * FF + k] : 0.0f;
            Wb[(size_t)t * NL * WSB + i] = __float2bfloat16(v);
        }
        return;
    }

    // ---- Ms path ----
    __shared__ float sv[128], red[128];
    __shared__ float s_w, s_it;
    int t = blk >> 6, l = blk & 63;
    if (c == 0) {
        float temp = expf(log_temp[0]);
        temp = fminf(fmaxf(temp, 0.1f), 5.0f);
        float it = 1.0f / temp;
        s_it = it;
        if (blk == 0) g_scalars[0] = it;
        float mx = -INFINITY;
        for (int i = 0; i < TT; i++) mx = fmaxf(mx, tw[i]);
        float s = 0.0f;
        for (int i = 0; i < TT; i++) s += expf(tw[i] - mx);
        s_w = expf(tw[t] - mx) / s;
    }
    __syncthreads();
    float v = (c < CC) ? leaf_logits[(size_t)blk * CC + c] * s_it : -INFINITY;
    sv[c] = v;
    red[c] = v;
    __syncthreads();
    for (int s = 64; s > 0; s >>= 1) {
        if (c < s) red[c] = fmaxf(red[c], red[c + s]);
        __syncthreads();
    }
    float mx = red[0];
    __syncthreads();
    float e = (c < CC) ? expf(v - mx) : 0.0f;
    red[c] = e;
    __syncthreads();
    for (int s = 64; s > 0; s >>= 1) {
        if (c < s) red[c] += red[c + s];
        __syncthreads();
    }
    float inv = 1.0f / red[0];
    if (c < CPAD) {
        float r = (c < CC) ? s_w * e * inv : 0.0f;
        __nv_bfloat16* Mb = (__nv_bfloat16*)g_Msbf;
        Mb[((size_t)t * CPAD + c) * MSB + l] = __float2bfloat16(r);
    }
}

// ---------------- prefetch helpers ------------------------------------------
__device__ __forceinline__ void prefetch_W(uint32_t sb32, int tid, int t, uint32_t slotOff) {
    const uint4* src = g_Wbf + (size_t)t * W_CP_CHUNKS;
#pragma unroll
    for (int m = 0; m < 9; m++) {
        int idx = tid + m * 256;
        if (idx < W_CP_CHUNKS) CP_ASYNC16(sb32 + slotOff + idx * 16, src + idx);
    }
    CP_COMMIT();
}
__device__ __forceinline__ void prefetch_Ms(uint32_t sb32, int tid, int t, uint32_t slotOff) {
    const uint4* src = g_Msbf + (size_t)t * MS_CP_CHUNKS;
#pragma unroll
    for (int m = 0; m < 4; m++) {
        int idx = tid + m * 256;
        if (idx < MS_CP_CHUNKS) CP_ASYNC16(sb32 + slotOff + idx * 16, src + idx);
    }
    CP_COMMIT();
}

// ---------------- main kernel ------------------------------------------------
__global__ __launch_bounds__(256, 1)
void main_kernel(const float* __restrict__ x,
                 const float* __restrict__ split_bias,
                 float* __restrict__ out) {
    extern __shared__ float sm[];
    char* smc = (char*)sm;
    const uint32_t sb32 = smem_u32(sm);
    float* plT   = (float*)(smc + OFF_PL);
    char*  lpB   = smc + OFF_LP;
    float* sbias = (float*)(smc + OFF_BIAS);
    const uint32_t* Xu = (const uint32_t*)(smc + OFF_X);
    const uint32_t* Lu = (const uint32_t*)(smc + OFF_LP);

    const int tid = threadIdx.x;
    const int wid = tid >> 5;
    const int lane = tid & 31;
    const int g = lane >> 2;
    const int tg = lane & 3;
    const int wr = wid & 3;
    const int wc = wid >> 2;
    const int nb2 = 7 - wc;            // GEMM2 n-blocks: wc=0 -> 7, wc=1 -> 6
    const int rowBase = blockIdx.x * BM;
    const int half = blockIdx.y;
    const float inv_temp = g_scalars[0];
    const int t0 = half * TPH;

    // ---- prologue: prefetch group A = W(0)+Ms(0); group B = W(1) ----
    {
        const uint4* wsrc = g_Wbf + (size_t)t0 * W_CP_CHUNKS;
        const uint4* msrc = g_Msbf + (size_t)t0 * MS_CP_CHUNKS;
#pragma unroll
        for (int m = 0; m < 9; m++) {
            int idx = tid + m * 256;
            if (idx < W_CP_CHUNKS) CP_ASYNC16(sb32 + OFF_W0 + idx * 16, wsrc + idx);
        }
#pragma unroll
        for (int m = 0; m < 4; m++) {
            int idx = tid + m * 256;
            if (idx < MS_CP_CHUNKS) CP_ASYNC16(sb32 + OFF_MS0 + idx * 16, msrc + idx);
        }
        CP_COMMIT();
        prefetch_W(sb32, tid, t0 + 1, OFF_W1);
    }

    // ---- stage X tile fp32 -> bf16 ----
#pragma unroll
    for (int m = 0; m < 32; m++) {
        int idx4 = tid + m * 256;          // row*64 + kc
        int row = idx4 >> 6, kc = idx4 & 63;
        float4 v = *(const float4*)(x + (size_t)(rowBase + row) * FF + kc * 4);
        uint32_t r0 = pack_bf16x2(v.y, v.x);
        uint32_t r1 = pack_bf16x2(v.w, v.z);
        *(uint2*)(smc + OFF_X + row * (XSB * 2) + kc * 8) = make_uint2(r0, r1);
    }
    // ---- stage all trees' bias ----
#pragma unroll
    for (int m = 0; m < 8; m++) {
        int i = tid + m * 256;
        int tb = i >> 6, node = i & 63;
        sbias[i] = (node < NI) ? split_bias[tb * NI + node] : 0.0f;
    }

    CP_WAIT1();            // W(0)+Ms(0) landed (W(1) may be in flight)
    __syncthreads();

    float d2[2][7][4];
#pragma unroll
    for (int mi = 0; mi < 2; mi++)
#pragma unroll
        for (int ni = 0; ni < 7; ni++)
#pragma unroll
            for (int e = 0; e < 4; e++) d2[mi][ni][e] = 0.0f;

    float d1[2][4][4];

    // ---- GEMM1 for a given W slot ----
    auto gemm1 = [&](uint32_t offW) {
        const uint32_t* Wu = (const uint32_t*)(smc + offW);
#pragma unroll
        for (int mi = 0; mi < 2; mi++)
#pragma unroll
            for (int ni = 0; ni < 4; ni++)
#pragma unroll
                for (int e = 0; e < 4; e++) d1[mi][ni][e] = 0.0f;
#pragma unroll 4
        for (int ks = 0; ks < 16; ks++) {
            const int kb = ks * 8;
            uint32_t a[2][4], b[4][2];
#pragma unroll
            for (int mi = 0; mi < 2; mi++) {
                int r0 = wr * 32 + mi * 16 + g;
                a[mi][0] = Xu[r0 * 132 + kb + tg];
                a[mi][1] = Xu[(r0 + 8) * 132 + kb + tg];
                a[mi][2] = Xu[r0 * 132 + kb + tg + 4];
                a[mi][3] = Xu[(r0 + 8) * 132 + kb + tg + 4];
            }
#pragma unroll
            for (int ni = 0; ni < 4; ni++) {
                int n0 = wc * 32 + ni * 8 + g;
                b[ni][0] = Wu[n0 * 132 + kb + tg];
                b[ni][1] = Wu[n0 * 132 + kb + tg + 4];
            }
#pragma unroll
            for (int mi = 0; mi < 2; mi++)
#pragma unroll
                for (int ni = 0; ni < 4; ni++) mma16(d1[mi][ni], a[mi], b[ni]);
        }
    };

    gemm1(OFF_W0);          // GEMM1(t0)

    for (int tt = 0; tt < TPH; tt++) {
        const int t = t0 + tt;
        const float* biasp = sbias + t * 64;

        // ---- sigmoid(t) from d1 -> plT ----
#pragma unroll
        for (int mi = 0; mi < 2; mi++) {
            int r0 = wr * 32 + mi * 16 + g;
#pragma unroll
            for (int ni = 0; ni < 4; ni++) {
                int n0 = wc * 32 + ni * 8 + 2 * tg;
#pragma unroll
                for (int e = 0; e < 4; e++) {
                    int r = r0 + (e >> 1) * 8;
                    int n = n0 + (e & 1);
                    float z = (d1[mi][ni][e] + biasp[n]) * inv_temp;
                    plT[r * PLS + n] = __fdividef(1.0f, 1.0f + __expf(-z));
                }
            }
        }
        __syncthreads();    // sync1: plT complete; GEMM2(t-1) done by all

        // ---- prefetch Ms(t+1) into slot (tt+1)&1 ----
        if (tt + 1 < TPH)
            prefetch_Ms(sb32, tid, t + 1, ((tt + 1) & 1) ? OFF_MS1 : OFF_MS0);

        // ---- heap climb (t): plT -> lpT bf16 ----
        for (int e = tid; e < (NL / 2) * BM; e += 256) {
            int j = e & 31;
            int row = e >> 5;
            const float* pl = plT + row * PLS;
            float pp = 1.0f;
#pragma unroll
            for (int d = 0; d < 5; d++) {
                int sub = j >> (4 - d);
                float gg = pl[((1 << d) - 1) + (j >> (5 - d))];
                pp *= (sub & 1) ? gg : (1.0f - gg);
            }
            float g6 = pl[31 + j];
            uint32_t pk = pack_bf16x2(pp * g6, pp * (1.0f - g6));
            *(uint32_t*)(lpB + row * 144 + j * 4) = pk;
        }

        if (tt == TPH - 1) CP_WAIT0(); else CP_WAIT1();
        __syncthreads();    // sync2: lpT complete; W(t+1), Ms(t) visible

        // ---- GEMM1(t+1) ----
        if (tt + 1 < TPH) gemm1(((tt + 1) & 1) ? OFF_W1 : OFF_W0);

        // ---- GEMM2(t): D2 += leafP @ Ms^T (128x104, K=64), asymmetric split --
        const uint32_t* Mu = (const uint32_t*)(smc + ((tt & 1) ? OFF_MS1 : OFF_MS0));
#pragma unroll
        for (int ks = 0; ks < 4; ks++) {
            const int kb = ks * 8;
            uint32_t a[2][4], b[7][2];
#pragma unroll
            for (int mi = 0; mi < 2; mi++) {
                int r0 = wr * 32 + mi * 16 + g;
                a[mi][0] = Lu[r0 * 36 + kb + tg];
                a[mi][1] = Lu[(r0 + 8) * 36 + kb + tg];
                a[mi][2] = Lu[r0 * 36 + kb + tg + 4];
                a[mi][3] = Lu[(r0 + 8) * 36 + kb + tg + 4];
            }
#pragma unroll
            for (int ni = 0; ni < 7; ni++) {
                if (ni < nb2) {
                    int n0 = wc * 56 + ni * 8 + g;
                    b[ni][0] = Mu[n0 * 36 + kb + tg];
                    b[ni][1] = Mu[n0 * 36 + kb + tg + 4];
                }
            }
#pragma unroll
            for (int mi = 0; mi < 2; mi++)
#pragma unroll
                for (int ni = 0; ni < 7; ni++)
                    if (ni < nb2) mma16(d2[mi][ni], a[mi], b[ni]);
        }

        // ---- prefetch W(t+2) into slot tt&1 (the slot gemm1(t+2) reads) ----
        if (tt + 2 < TPH)
            prefetch_W(sb32, tid, t + 2, (tt & 1) ? OFF_W1 : OFF_W0);
    }

    // ---- epilogue: atomic accumulate into out (exactly 2 adders/element;
    //      0 + a + b is order-invariant => deterministic) ----
#pragma unroll
    for (int mi = 0; mi < 2; mi++) {
#pragma unroll
        for (int e2 = 0; e2 < 2; e2++) {
            int row = rowBase + wr * 32 + mi * 16 + g + e2 * 8;
            float* op = out + (size_t)row * CC;
#pragma unroll
            for (int ni = 0; ni < 7; ni++) {
                if (ni < nb2) {
                    int col = wc * 56 + ni * 8 + 2 * tg;
                    if (col < CC)     atomicAdd(op + col,     d2[mi][ni][e2 * 2]);
                    if (col + 1 < CC) atomicAdd(op + col + 1, d2[mi][ni][e2 * 2 + 1]);
                }
            }
        }
    }
}

// ---------------- launch -----------------------------------------------------
extern "C" void kernel_launch(void* const* d_in, const int* in_sizes, int n_in,
                              void* d_out, int out_size) {
    const float* x          = nullptr;   // 2097152
    const float* split_w    = nullptr;   // 516096
    const float* split_bias = nullptr;   // 2016
    const float* leaf_log   = nullptr;   // 204800
    const float* tree_w     = nullptr;   // 32
    const float* log_temp   = nullptr;   // 1
    for (int i = 0; i < n_in; i++) {
        switch (in_sizes[i]) {
            case BN * FF:      x          = (const float*)d_in[i]; break;
            case TT * NI * FF: split_w    = (const float*)d_in[i]; break;
            case TT * NI:      split_bias = (const float*)d_in[i]; break;
            case TT * NL * CC: leaf_log   = (const float*)d_in[i]; break;
            case TT:           tree_w     = (const float*)d_in[i]; break;
            case 1:            log_temp   = (const float*)d_in[i]; break;
            default: break;
        }
    }
    if (!x)          x          = (const float*)d_in[0];
    if (!split_w)    split_w    = (const float*)d_in[1];
    if (!split_bias) split_bias = (const float*)d_in[2];
    if (!leaf_log)   leaf_log   = (const float*)d_in[3];
    if (!tree_w)     tree_w     = (const float*)d_in[4];
    if (!log_temp)   log_temp   = (const float*)d_in[5];
    float* out = (float*)d_out;

    prep_kernel<<<TT * NL + TT, 128>>>(leaf_log, tree_w, log_temp, split_w);
    cudaMemsetAsync(out, 0, (size_t)out_size * sizeof(float), 0);

    cudaFuncSetAttribute(main_kernel,
                         cudaFuncAttributeMaxDynamicSharedMemorySize, SMEM_BYTES);
    dim3 grid(BN / BM, NHALF);
    main_kernel<<<grid, 256, SMEM_BYTES>>>(x, split_bias, out);
}

// round 15
// speedup vs baseline: 4.8915x; 1.0423x over previous
#include <cuda_runtime.h>
#include <cuda_bf16.h>
#include <math.h>
#include <stdint.h>

// Problem constants  (B,F,T,C = 8192, 256, 32, 100)
#define BN 8192
#define FF 256
#define TT 32
#define NI 63
#define NL 64
#define CC 100
#define CPAD 104          // padded class dim (13 x 8)

#define BM 128            // batch rows per CTA
#define NHALF 2
#define TPH (TT / NHALF)  // 16 trees per CTA

// bf16 smem strides
#define XSB 264           // X row stride in bf16   (528 B)
#define WSB 264           // W node stride in bf16  (528 B)
#define MSB 72            // Ms class stride in bf16 (144 B)
#define PLS 65            // plT row stride in fp32

// smem byte offsets
#define OFF_X    0                      // 128*528 = 67584
#define OFF_W0   67584                  // 64*528  = 33792
#define OFF_W1   101376
#define OFF_MS0  135168                 // 104*144 = 14976
#define OFF_MS1  150144
#define OFF_PL   165120                 // 128*65*4 = 33280
#define OFF_LP   198400                 // 128*144  = 18432
#define OFF_BIAS 216832                 // 32*64*4  = 8192
#define SMEM_BYTES 225024

#define W_CP_CHUNKS  2112               // 33792/16
#define MS_CP_CHUNKS 936                // 14976/16

__device__ __forceinline__ uint32_t smem_u32(const void* p) {
    uint32_t a;
    asm("{ .reg .u64 t; cvta.to.shared.u64 t, %1; cvt.u32.u64 %0, t; }" : "=r"(a) : "l"(p));
    return a;
}
#define CP_ASYNC16(dst, src) \
    asm volatile("cp.async.cg.shared.global [%0], [%1], 16;" :: "r"(dst), "l"(src) : "memory")
#define CP_COMMIT() asm volatile("cp.async.commit_group;" ::: "memory")
#define CP_WAIT1()  asm volatile("cp.async.wait_group 1;" ::: "memory")
#define CP_WAIT0()  asm volatile("cp.async.wait_group 0;" ::: "memory")

__device__ __forceinline__ uint32_t pack_bf16x2(float hi, float lo) {
    uint32_t r;
    asm("cvt.rn.bf16x2.f32 %0, %1, %2;" : "=r"(r) : "f"(hi), "f"(lo));
    return r;
}

__device__ __forceinline__ void mma16(float d[4], const uint32_t a[4], const uint32_t b[2]) {
    asm volatile(
        "mma.sync.aligned.m16n8k16.row.col.f32.bf16.bf16.f32 "
        "{%0,%1,%2,%3}, {%4,%5,%6,%7}, {%8,%9}, {%0,%1,%2,%3};"
        : "+f"(d[0]), "+f"(d[1]), "+f"(d[2]), "+f"(d[3])
        : "r"(a[0]), "r"(a[1]), "r"(a[2]), "r"(a[3]), "r"(b[0]), "r"(b[1]));
}
__device__ __forceinline__ void ldsm4(uint32_t r[4], uint32_t addr) {
    asm volatile("ldmatrix.sync.aligned.m8n8.x4.shared.b16 {%0,%1,%2,%3}, [%4];"
        : "=r"(r[0]), "=r"(r[1]), "=r"(r[2]), "=r"(r[3]) : "r"(addr));
}
__device__ __forceinline__ void ldsm2(uint32_t r[2], uint32_t addr) {
    asm volatile("ldmatrix.sync.aligned.m8n8.x2.shared.b16 {%0,%1}, [%2];"
        : "=r"(r[0]), "=r"(r[1]) : "r"(addr));
}

// ---------------- scratch ----------------------------------------------------
__device__ float g_scalars[4];
__device__ uint4 g_Wbf[TT * W_CP_CHUNKS];     // [t][node(64)][k stride 264] bf16
__device__ uint4 g_Msbf[TT * MS_CP_CHUNKS];   // [t][class(104)][leaf stride 72] bf16

// ---------------- merged prep: Ms build (blocks 0..2047) + W cvt (2048..) ---
__global__ void prep_kernel(const float* __restrict__ leaf_logits,
                            const float* __restrict__ tw,
                            const float* __restrict__ log_temp,
                            const float* __restrict__ W) {
    int blk = blockIdx.x;
    int c = threadIdx.x;               // 0..127

    if (blk >= TT * NL) {              // ---- W conversion path ----
        int t = blk - TT * NL;
        __nv_bfloat16* Wb = (__nv_bfloat16*)g_Wbf;
        for (int i = c; i < NL * WSB; i += 128) {
            int node = i / WSB;
            int k = i - node * WSB;
            float v = (node < NI && k < FF) ? W[((size_t)t * NI + node) * FF + k] : 0.0f;
            Wb[(size_t)t * NL * WSB + i] = __float2bfloat16(v);
        }
        return;
    }

    // ---- Ms path ----
    __shared__ float sv[128], red[128];
    __shared__ float s_w, s_it;
    int t = blk >> 6, l = blk & 63;
    if (c == 0) {
        float temp = expf(log_temp[0]);
        temp = fminf(fmaxf(temp, 0.1f), 5.0f);
        float it = 1.0f / temp;
        s_it = it;
        if (blk == 0) g_scalars[0] = it;
        float mx = -INFINITY;
        for (int i = 0; i < TT; i++) mx = fmaxf(mx, tw[i]);
        float s = 0.0f;
        for (int i = 0; i < TT; i++) s += expf(tw[i] - mx);
        s_w = expf(tw[t] - mx) / s;
    }
    __syncthreads();
    float v = (c < CC) ? leaf_logits[(size_t)blk * CC + c] * s_it : -INFINITY;
    sv[c] = v;
    red[c] = v;
    __syncthreads();
    for (int s = 64; s > 0; s >>= 1) {
        if (c < s) red[c] = fmaxf(red[c], red[c + s]);
        __syncthreads();
    }
    float mx = red[0];
    __syncthreads();
    float e = (c < CC) ? expf(v - mx) : 0.0f;
    red[c] = e;
    __syncthreads();
    for (int s = 64; s > 0; s >>= 1) {
        if (c < s) red[c] += red[c + s];
        __syncthreads();
    }
    float inv = 1.0f / red[0];
    if (c < CPAD) {
        float r = (c < CC) ? s_w * e * inv : 0.0f;
        __nv_bfloat16* Mb = (__nv_bfloat16*)g_Msbf;
        Mb[((size_t)t * CPAD + c) * MSB + l] = __float2bfloat16(r);
    }
}

// ---------------- prefetch helpers ------------------------------------------
__device__ __forceinline__ void prefetch_W(uint32_t sb32, int tid, int t, uint32_t slotOff) {
    const uint4* src = g_Wbf + (size_t)t * W_CP_CHUNKS;
#pragma unroll
    for (int m = 0; m < 9; m++) {
        int idx = tid + m * 256;
        if (idx < W_CP_CHUNKS) CP_ASYNC16(sb32 + slotOff + idx * 16, src + idx);
    }
    CP_COMMIT();
}
__device__ __forceinline__ void prefetch_Ms(uint32_t sb32, int tid, int t, uint32_t slotOff) {
    const uint4* src = g_Msbf + (size_t)t * MS_CP_CHUNKS;
#pragma unroll
    for (int m = 0; m < 4; m++) {
        int idx = tid + m * 256;
        if (idx < MS_CP_CHUNKS) CP_ASYNC16(sb32 + slotOff + idx * 16, src + idx);
    }
    CP_COMMIT();
}

// ---------------- main kernel ------------------------------------------------
__global__ __launch_bounds__(256, 1)
void main_kernel(const float* __restrict__ x,
                 const float* __restrict__ split_bias,
                 float* __restrict__ out) {
    extern __shared__ float sm[];
    char* smc = (char*)sm;
    const uint32_t sb32 = smem_u32(sm);
    float* plT   = (float*)(smc + OFF_PL);
    char*  lpB   = smc + OFF_LP;
    float* sbias = (float*)(smc + OFF_BIAS);

    const int tid = threadIdx.x;
    const int wid = tid >> 5;
    const int lane = tid & 31;
    const int g = lane >> 2;
    const int tg = lane & 3;
    const int wr = wid & 3;
    const int wc = wid >> 2;
    const int nb2 = 7 - wc;            // GEMM2 n-blocks: wc=0 -> 7, wc=1 -> 6
    const int rowBase = blockIdx.x * BM;
    const int half = blockIdx.y;
    const float inv_temp = g_scalars[0];
    const int t0 = half * TPH;

    // ldmatrix lane-address bases
    const int lrow8  = ((lane >> 3) & 1) * 8 + (lane & 7);   // row-within-16
    const int lkhalf = (lane >> 4);                          // k-half select
    // GEMM1 A (X): rows wr*32 + mi*16 + lrow8, k byte = lkhalf*16 + ks*32
    const uint32_t aBase1 = sb32 + OFF_X
        + (uint32_t)(wr * 32 + lrow8) * 528 + (uint32_t)lkhalf * 16;
    // GEMM1 B (W): nodes wc*32 + pair*16 + (lane>>4)*8 + (lane&7), khalf=(lane>>3)&1
    const uint32_t bLane1 = (uint32_t)((lane >> 4) * 8 + (lane & 7)) * 528
        + (uint32_t)((lane >> 3) & 1) * 16 + (uint32_t)(wc * 32) * 528;
    // GEMM2 A (lpT): rows wr*32 + mi*16 + lrow8
    const uint32_t aBase2 = sb32 + OFF_LP
        + (uint32_t)(wr * 32 + lrow8) * 144 + (uint32_t)lkhalf * 16;
    // GEMM2 B (Ms): classes wc*56 + pair*16 + (lane>>4)*8 + (lane&7)
    const uint32_t bLane2 = (uint32_t)((lane >> 4) * 8 + (lane & 7)) * 144
        + (uint32_t)((lane >> 3) & 1) * 16 + (uint32_t)(wc * 56) * 144;

    // ---- prologue: prefetch group A = W(0)+Ms(0); group B = W(1) ----
    {
        const uint4* wsrc = g_Wbf + (size_t)t0 * W_CP_CHUNKS;
        const uint4* msrc = g_Msbf + (size_t)t0 * MS_CP_CHUNKS;
#pragma unroll
        for (int m = 0; m < 9; m++) {
            int idx = tid + m * 256;
            if (idx < W_CP_CHUNKS) CP_ASYNC16(sb32 + OFF_W0 + idx * 16, wsrc + idx);
        }
#pragma unroll
        for (int m = 0; m < 4; m++) {
            int idx = tid + m * 256;
            if (idx < MS_CP_CHUNKS) CP_ASYNC16(sb32 + OFF_MS0 + idx * 16, msrc + idx);
        }
        CP_COMMIT();
        prefetch_W(sb32, tid, t0 + 1, OFF_W1);
    }

    // ---- stage X tile fp32 -> bf16 ----
#pragma unroll
    for (int m = 0; m < 32; m++) {
        int idx4 = tid + m * 256;          // row*64 + kc
        int row = idx4 >> 6, kc = idx4 & 63;
        float4 v = *(const float4*)(x + (size_t)(rowBase + row) * FF + kc * 4);
        uint32_t r0 = pack_bf16x2(v.y, v.x);
        uint32_t r1 = pack_bf16x2(v.w, v.z);
        *(uint2*)(smc + OFF_X + row * (XSB * 2) + kc * 8) = make_uint2(r0, r1);
    }
    // ---- stage all trees' bias ----
#pragma unroll
    for (int m = 0; m < 8; m++) {
        int i = tid + m * 256;
        int tb = i >> 6, node = i & 63;
        sbias[i] = (node < NI) ? split_bias[tb * NI + node] : 0.0f;
    }

    CP_WAIT1();            // W(0)+Ms(0) landed (W(1) may be in flight)
    __syncthreads();

    float d2[2][7][4];
#pragma unroll
    for (int mi = 0; mi < 2; mi++)
#pragma unroll
        for (int ni = 0; ni < 7; ni++)
#pragma unroll
            for (int e = 0; e < 4; e++) d2[mi][ni][e] = 0.0f;

    float d1[2][4][4];

    // ---- GEMM1 via ldmatrix fragments ----
    auto gemm1 = [&](uint32_t offW) {
        const uint32_t bBase = sb32 + offW + bLane1;
#pragma unroll
        for (int mi = 0; mi < 2; mi++)
#pragma unroll
            for (int ni = 0; ni < 4; ni++)
#pragma unroll
                for (int e = 0; e < 4; e++) d1[mi][ni][e] = 0.0f;
#pragma unroll 4
        for (int ks = 0; ks < 16; ks++) {
            uint32_t a[2][4], bq0[4], bq1[4];
            ldsm4(a[0], aBase1 + ks * 32);
            ldsm4(a[1], aBase1 + 16 * 528 + ks * 32);
            ldsm4(bq0, bBase + ks * 32);                 // nodes pair 0 (ni 0,1)
            ldsm4(bq1, bBase + 16 * 528 + ks * 32);      // nodes pair 1 (ni 2,3)
#pragma unroll
            for (int mi = 0; mi < 2; mi++) {
                mma16(d1[mi][0], a[mi], &bq0[0]);
                mma16(d1[mi][1], a[mi], &bq0[2]);
                mma16(d1[mi][2], a[mi], &bq1[0]);
                mma16(d1[mi][3], a[mi], &bq1[2]);
            }
        }
    };

    gemm1(OFF_W0);          // GEMM1(t0)

    for (int tt = 0; tt < TPH; tt++) {
        const int t = t0 + tt;
        const float* biasp = sbias + t * 64;

        // ---- sigmoid(t) from d1 -> plT ----
#pragma unroll
        for (int mi = 0; mi < 2; mi++) {
            int r0 = wr * 32 + mi * 16 + g;
#pragma unroll
            for (int ni = 0; ni < 4; ni++) {
                int n0 = wc * 32 + ni * 8 + 2 * tg;
#pragma unroll
                for (int e = 0; e < 4; e++) {
                    int r = r0 + (e >> 1) * 8;
                    int n = n0 + (e & 1);
                    float z = (d1[mi][ni][e] + biasp[n]) * inv_temp;
                    plT[r * PLS + n] = __fdividef(1.0f, 1.0f + __expf(-z));
                }
            }
        }
        __syncthreads();    // sync1: plT complete; GEMM2(t-1) done by all

        // ---- prefetch Ms(t+1) into slot (tt+1)&1 ----
        if (tt + 1 < TPH)
            prefetch_Ms(sb32, tid, t + 1, ((tt + 1) & 1) ? OFF_MS1 : OFF_MS0);

        // ---- heap climb (t): plT -> lpT bf16 ----
        for (int e = tid; e < (NL / 2) * BM; e += 256) {
            int j = e & 31;
            int row = e >> 5;
            const float* pl = plT + row * PLS;
            float pp = 1.0f;
#pragma unroll
            for (int d = 0; d < 5; d++) {
                int sub = j >> (4 - d);
                float gg = pl[((1 << d) - 1) + (j >> (5 - d))];
                pp *= (sub & 1) ? gg : (1.0f - gg);
            }
            float g6 = pl[31 + j];
            uint32_t pk = pack_bf16x2(pp * g6, pp * (1.0f - g6));
            *(uint32_t*)(lpB + row * 144 + j * 4) = pk;
        }

        if (tt == TPH - 1) CP_WAIT0(); else CP_WAIT1();
        __syncthreads();    // sync2: lpT complete; W(t+1), Ms(t) visible

        // ---- GEMM1(t+1) ----
        if (tt + 1 < TPH) gemm1(((tt + 1) & 1) ? OFF_W1 : OFF_W0);

        // ---- GEMM2(t): D2 += leafP @ Ms^T (128x104, K=64), ldmatrix ----
        const uint32_t bBase2 = sb32 + ((tt & 1) ? OFF_MS1 : OFF_MS0) + bLane2;
#pragma unroll
        for (int ks = 0; ks < 4; ks++) {
            uint32_t a[2][4], bq0[4], bq1[4], bq2[4], bq3[2];
            ldsm4(a[0], aBase2 + ks * 32);
            ldsm4(a[1], aBase2 + 16 * 144 + ks * 32);
            ldsm4(bq0, bBase2 + ks * 32);                // classes pair 0 (ni 0,1)
            ldsm4(bq1, bBase2 + 16 * 144 + ks * 32);     // ni 2,3
            ldsm4(bq2, bBase2 + 32 * 144 + ks * 32);     // ni 4,5
            if (wc == 0) ldsm2(bq3, bBase2 + 48 * 144 + ks * 32);  // ni 6
#pragma unroll
            for (int mi = 0; mi < 2; mi++) {
                mma16(d2[mi][0], a[mi], &bq0[0]);
                mma16(d2[mi][1], a[mi], &bq0[2]);
                mma16(d2[mi][2], a[mi], &bq1[0]);
                mma16(d2[mi][3], a[mi], &bq1[2]);
                mma16(d2[mi][4], a[mi], &bq2[0]);
                mma16(d2[mi][5], a[mi], &bq2[2]);
                if (wc == 0) mma16(d2[mi][6], a[mi], &bq3[0]);
            }
        }

        // ---- prefetch W(t+2) into slot tt&1 (the slot gemm1(t+2) reads) ----
        if (tt + 2 < TPH)
            prefetch_W(sb32, tid, t + 2, (tt & 1) ? OFF_W1 : OFF_W0);
    }

    // ---- epilogue: atomic accumulate into out (2 adders/element onto 0 —
    //      order-invariant => deterministic) ----
#pragma unroll
    for (int mi = 0; mi < 2; mi++) {
#pragma unroll
        for (int e2 = 0; e2 < 2; e2++) {
            int row = rowBase + wr * 32 + mi * 16 + g + e2 * 8;
            float* op = out + (size_t)row * CC;
#pragma unroll
            for (int ni = 0; ni < 7; ni++) {
                if (ni < nb2) {
                    int col = wc * 56 + ni * 8 + 2 * tg;
                    if (col < CC)     atomicAdd(op + col,     d2[mi][ni][e2 * 2]);
                    if (col + 1 < CC) atomicAdd(op + col + 1, d2[mi][ni][e2 * 2 + 1]);
                }
            }
        }
    }
}

// ---------------- launch -----------------------------------------------------
extern "C" void kernel_launch(void* const* d_in, const int* in_sizes, int n_in,
                              void* d_out, int out_size) {
    const float* x          = nullptr;   // 2097152
    const float* split_w    = nullptr;   // 516096
    const float* split_bias = nullptr;   // 2016
    const float* leaf_log   = nullptr;   // 204800
    const float* tree_w     = nullptr;   // 32
    const float* log_temp   = nullptr;   // 1
    for (int i = 0; i < n_in; i++) {
        switch (in_sizes[i]) {
            case BN * FF:      x          = (const float*)d_in[i]; break;
            case TT * NI * FF: split_w    = (const float*)d_in[i]; break;
            case TT * NI:      split_bias = (const float*)d_in[i]; break;
            case TT * NL * CC: leaf_log   = (const float*)d_in[i]; break;
            case TT:           tree_w     = (const float*)d_in[i]; break;
            case 1:            log_temp   = (const float*)d_in[i]; break;
            default: break;
        }
    }
    if (!x)          x          = (const float*)d_in[0];
    if (!split_w)    split_w    = (const float*)d_in[1];
    if (!split_bias) split_bias = (const float*)d_in[2];
    if (!leaf_log)   leaf_log   = (const float*)d_in[3];
    if (!tree_w)     tree_w     = (const float*)d_in[4];
    if (!log_temp)   log_temp   = (const float*)d_in[5];
    float* out = (float*)d_out;

    prep_kernel<<<TT * NL + TT, 128>>>(leaf_log, tree_w, log_temp, split_w);
    cudaMemsetAsync(out, 0, (size_t)out_size * sizeof(float), 0);

    cudaFuncSetAttribute(main_kernel,
                         cudaFuncAttributeMaxDynamicSharedMemorySize, SMEM_BYTES);
    dim3 grid(BN / BM, NHALF);
    main_kernel<<<grid, 256, SMEM_BYTES>>>(x, split_bias, out);
}

// round 16
// speedup vs baseline: 5.3441x; 1.0925x over previous
#include <cuda_runtime.h>
#include <cuda_bf16.h>
#include <math.h>
#include <stdint.h>

// Problem constants  (B,F,T,C = 8192, 256, 32, 100)
#define BN 8192
#define FF 256
#define TT 32
#define NI 63
#define NL 64
#define CC 100
#define CPAD 104          // padded class dim (13 x 8)

#define BM 64             // batch rows per CTA
#define NHALF 2
#define TPH (TT / NHALF)  // 16 trees per CTA

// bf16 smem strides (bytes per row)
#define XROW 528          // 264 bf16
#define WROW 528
#define MROW 144          // 72 bf16
#define LROW 144
#define PLS 65            // plT row stride in fp32 words

// smem byte offsets (total 112512 B = 109.9 KB -> 2 CTAs/SM)
#define OFF_X    0                      // 64*528  = 33792
#define OFF_W    33792                  // 64*528  = 33792
#define OFF_MS   67584                  // 104*144 = 14976
#define OFF_PL   82560                  // 64*65*4 = 16640
#define OFF_LP   99200                  // 64*144  = 9216
#define OFF_BIAS 108416                 // 16*64*4 = 4096
#define SMEM_BYTES 112512

#define W_CP_CHUNKS  2112               // 33792/16
#define MS_CP_CHUNKS 936                // 14976/16

__device__ __forceinline__ uint32_t smem_u32(const void* p) {
    uint32_t a;
    asm("{ .reg .u64 t; cvta.to.shared.u64 t, %1; cvt.u32.u64 %0, t; }" : "=r"(a) : "l"(p));
    return a;
}
#define CP_ASYNC16(dst, src) \
    asm volatile("cp.async.cg.shared.global [%0], [%1], 16;" :: "r"(dst), "l"(src) : "memory")
#define CP_COMMIT() asm volatile("cp.async.commit_group;" ::: "memory")
#define CP_WAIT1()  asm volatile("cp.async.wait_group 1;" ::: "memory")
#define CP_WAIT0()  asm volatile("cp.async.wait_group 0;" ::: "memory")

__device__ __forceinline__ uint32_t pack_bf16x2(float hi, float lo) {
    uint32_t r;
    asm("cvt.rn.bf16x2.f32 %0, %1, %2;" : "=r"(r) : "f"(hi), "f"(lo));
    return r;
}
__device__ __forceinline__ float fast_sigmoid(float z) {
    float t;
    asm("tanh.approx.f32 %0, %1;" : "=f"(t) : "f"(z * 0.5f));
    return fmaf(t, 0.5f, 0.5f);
}

__device__ __forceinline__ void mma16(float d[4], const uint32_t a[4], const uint32_t b[2]) {
    asm volatile(
        "mma.sync.aligned.m16n8k16.row.col.f32.bf16.bf16.f32 "
        "{%0,%1,%2,%3}, {%4,%5,%6,%7}, {%8,%9}, {%0,%1,%2,%3};"
        : "+f"(d[0]), "+f"(d[1]), "+f"(d[2]), "+f"(d[3])
        : "r"(a[0]), "r"(a[1]), "r"(a[2]), "r"(a[3]), "r"(b[0]), "r"(b[1]));
}
__device__ __forceinline__ void ldsm4(uint32_t r[4], uint32_t addr) {
    asm volatile("ldmatrix.sync.aligned.m8n8.x4.shared.b16 {%0,%1,%2,%3}, [%4];"
        : "=r"(r[0]), "=r"(r[1]), "=r"(r[2]), "=r"(r[3]) : "r"(addr));
}
__device__ __forceinline__ void ldsm2(uint32_t r[2], uint32_t addr) {
    asm volatile("ldmatrix.sync.aligned.m8n8.x2.shared.b16 {%0,%1}, [%2];"
        : "=r"(r[0]), "=r"(r[1]) : "r"(addr));
}

// ---------------- scratch ----------------------------------------------------
__device__ float g_scalars[4];
__device__ uint4 g_Wbf[TT * W_CP_CHUNKS];     // [t][node(64)][k stride 264] bf16
__device__ uint4 g_Msbf[TT * MS_CP_CHUNKS];   // [t][class(104)][leaf stride 72] bf16

// ---------------- merged prep: Ms build (blocks 0..2047) + W cvt (2048..) ---
__global__ void prep_kernel(const float* __restrict__ leaf_logits,
                            const float* __restrict__ tw,
                            const float* __restrict__ log_temp,
                            const float* __restrict__ W) {
    int blk = blockIdx.x;
    int c = threadIdx.x;               // 0..127

    if (blk >= TT * NL) {              // ---- W conversion path ----
        int t = blk - TT * NL;
        __nv_bfloat16* Wb = (__nv_bfloat16*)g_Wbf;
        for (int i = c; i < NL * 264; i += 128) {
            int node = i / 264;
            int k = i - node * 264;
            float v = (node < NI && k < FF) ? W[((size_t)t * NI + node) * FF + k] : 0.0f;
            Wb[(size_t)t * NL * 264 + i] = __float2bfloat16(v);
        }
        return;
    }

    // ---- Ms path ----
    __shared__ float sv[128], red[128];
    __shared__ float s_w, s_it;
    int t = blk >> 6, l = blk & 63;
    if (c == 0) {
        float temp = expf(log_temp[0]);
        temp = fminf(fmaxf(temp, 0.1f), 5.0f);
        float it = 1.0f / temp;
        s_it = it;
        if (blk == 0) g_scalars[0] = it;
        float mx = -INFINITY;
        for (int i = 0; i < TT; i++) mx = fmaxf(mx, tw[i]);
        float s = 0.0f;
        for (int i = 0; i < TT; i++) s += expf(tw[i] - mx);
        s_w = expf(tw[t] - mx) / s;
    }
    __syncthreads();
    float v = (c < CC) ? leaf_logits[(size_t)blk * CC + c] * s_it : -INFINITY;
    sv[c] = v;
    red[c] = v;
    __syncthreads();
    for (int s = 64; s > 0; s >>= 1) {
        if (c < s) red[c] = fmaxf(red[c], red[c + s]);
        __syncthreads();
    }
    float mx = red[0];
    __syncthreads();
    float e = (c < CC) ? expf(v - mx) : 0.0f;
    red[c] = e;
    __syncthreads();
    for (int s = 64; s > 0; s >>= 1) {
        if (c < s) red[c] += red[c + s];
        __syncthreads();
    }
    float inv = 1.0f / red[0];
    if (c < CPAD) {
        float r = (c < CC) ? s_w * e * inv : 0.0f;
        __nv_bfloat16* Mb = (__nv_bfloat16*)g_Msbf;
        Mb[((size_t)t * CPAD + c) * 72 + l] = __float2bfloat16(r);
    }
}

// ---------------- prefetch helpers (commit done by caller) -------------------
__device__ __forceinline__ void issue_W(uint32_t sb32, int tid, int t) {
    const uint4* src = g_Wbf + (size_t)t * W_CP_CHUNKS;
#pragma unroll
    for (int m = 0; m < 9; m++) {
        int idx = tid + m * 256;
        if (idx < W_CP_CHUNKS) CP_ASYNC16(sb32 + OFF_W + idx * 16, src + idx);
    }
}
__device__ __forceinline__ void issue_Ms(uint32_t sb32, int tid, int t) {
    const uint4* src = g_Msbf + (size_t)t * MS_CP_CHUNKS;
#pragma unroll
    for (int m = 0; m < 4; m++) {
        int idx = tid + m * 256;
        if (idx < MS_CP_CHUNKS) CP_ASYNC16(sb32 + OFF_MS + idx * 16, src + idx);
    }
}

// ---------------- main kernel ------------------------------------------------
__global__ __launch_bounds__(256, 2)
void main_kernel(const float* __restrict__ x,
                 const float* __restrict__ split_bias,
                 float* __restrict__ out) {
    extern __shared__ float sm[];
    char* smc = (char*)sm;
    const uint32_t sb32 = smem_u32(sm);
    float* plT   = (float*)(smc + OFF_PL);
    char*  lpB   = smc + OFF_LP;
    float* sbias = (float*)(smc + OFF_BIAS);

    const int tid = threadIdx.x;
    const int wid = tid >> 5;
    const int lane = tid & 31;
    const int g = lane >> 2;
    const int tg = lane & 3;
    const int wr = wid & 3;            // row block (16 rows)
    const int wc = wid >> 2;           // col half
    const int nb2 = 7 - wc;            // GEMM2 n-blocks: wc=0 -> 7, wc=1 -> 6
    const int rowBase = blockIdx.x * BM;
    const int half = blockIdx.y;
    const float inv_temp = g_scalars[0];
    const int t0 = half * TPH;

    // ldmatrix lane-address components
    const int lrow8  = ((lane >> 3) & 1) * 8 + (lane & 7);
    const int lkhalf = (lane >> 4);
    const uint32_t aBase1 = sb32 + OFF_X
        + (uint32_t)(wr * 16 + lrow8) * XROW + (uint32_t)lkhalf * 16;
    const uint32_t bBase1 = sb32 + OFF_W
        + (uint32_t)(wc * 32 + (lane >> 4) * 8 + (lane & 7)) * WROW
        + (uint32_t)((lane >> 3) & 1) * 16;
    const uint32_t aBase2 = sb32 + OFF_LP
        + (uint32_t)(wr * 16 + lrow8) * LROW + (uint32_t)lkhalf * 16;
    const uint32_t bBase2 = sb32 + OFF_MS
        + (uint32_t)(wc * 56 + (lane >> 4) * 8 + (lane & 7)) * MROW
        + (uint32_t)((lane >> 3) & 1) * 16;

    // ---- prologue: W(0)+Ms(0) as one group ----
    issue_W(sb32, tid, t0);
    issue_Ms(sb32, tid, t0);
    CP_COMMIT();

    // ---- stage X tile fp32 -> bf16 (64 rows) ----
#pragma unroll
    for (int m = 0; m < 16; m++) {
        int idx4 = tid + m * 256;          // row*64 + kc
        int row = idx4 >> 6, kc = idx4 & 63;
        float4 v = *(const float4*)(x + (size_t)(rowBase + row) * FF + kc * 4);
        uint32_t r0 = pack_bf16x2(v.y, v.x);
        uint32_t r1 = pack_bf16x2(v.w, v.z);
        *(uint2*)(smc + OFF_X + row * XROW + kc * 8) = make_uint2(r0, r1);
    }
    // ---- stage this half's bias (16 trees) ----
#pragma unroll
    for (int m = 0; m < 4; m++) {
        int i = tid + m * 256;             // tt*64 + node
        int tb = t0 + (i >> 6), node = i & 63;
        sbias[i] = (node < NI) ? split_bias[tb * NI + node] : 0.0f;
    }

    CP_WAIT0();
    __syncthreads();

    float d2[2][7][4];                     // [padding mi kept 1][7 n-blocks]
    float d1[4][4];
#pragma unroll
    for (int ni = 0; ni < 7; ni++)
#pragma unroll
        for (int e = 0; e < 4; e++) { d2[0][ni][e] = 0.0f; d2[1][ni][e] = 0.0f; }
    // only d2[0] used (16 rows/warp); keep array small:
    // (d2[1] optimized away by compiler since never stored)

    for (int tt = 0; tt < TPH; tt++) {
        const float* biasp = sbias + tt * 64;

        // ---- GEMM1(t): d1 = X @ W^T (16 rows x 32 nodes per warp, K=256) ----
#pragma unroll
        for (int ni = 0; ni < 4; ni++)
#pragma unroll
            for (int e = 0; e < 4; e++) d1[ni][e] = 0.0f;
#pragma unroll 4
        for (int ks = 0; ks < 16; ks++) {
            uint32_t a[4], bq0[4], bq1[4];
            ldsm4(a, aBase1 + ks * 32);
            ldsm4(bq0, bBase1 + ks * 32);
            ldsm4(bq1, bBase1 + 16 * WROW + ks * 32);
            mma16(d1[0], a, &bq0[0]);
            mma16(d1[1], a, &bq0[2]);
            mma16(d1[2], a, &bq1[0]);
            mma16(d1[3], a, &bq1[2]);
        }

        // ---- sigmoid -> plT ----
#pragma unroll
        for (int ni = 0; ni < 4; ni++) {
            int n0 = wc * 32 + ni * 8 + 2 * tg;
#pragma unroll
            for (int e = 0; e < 4; e++) {
                int r = wr * 16 + g + (e >> 1) * 8;
                int n = n0 + (e & 1);
                float z = (d1[ni][e] + biasp[n]) * inv_temp;
                plT[r * PLS + n] = fast_sigmoid(z);
            }
        }
        __syncthreads();    // sync1: W reads done, plT complete

        // ---- prefetch W(t+1) into the (now free) W buffer ----
        if (tt + 1 < TPH) { issue_W(sb32, tid, t0 + tt + 1); CP_COMMIT(); }

        // ---- heap climb: plT -> lpT bf16 (leaf pairs) ----
        for (int e = tid; e < (NL / 2) * BM; e += 256) {   // 8 iters
            int j = e & 31;
            int row = e >> 5;
            const float* pl = plT + row * PLS;
            float pp = 1.0f;
#pragma unroll
            for (int d = 0; d < 5; d++) {
                int sub = j >> (4 - d);
                float gg = pl[((1 << d) - 1) + (j >> (5 - d))];
                pp *= (sub & 1) ? gg : (1.0f - gg);
            }
            float g6 = pl[31 + j];
            uint32_t pk = pack_bf16x2(pp * g6, pp * (1.0f - g6));
            *(uint32_t*)(lpB + row * LROW + j * 4) = pk;
        }
        // ensure Ms(t) landed (allow W(t+1) in flight)
        if (tt + 1 < TPH) CP_WAIT1(); else CP_WAIT0();
        __syncthreads();    // sync2: lpT ready, Ms(t) visible

        // ---- GEMM2(t): d2 += leafP @ Ms^T (16 rows x 56/48 classes, K=64) --
#pragma unroll
        for (int ks = 0; ks < 4; ks++) {
            uint32_t a[4], bq0[4], bq1[4], bq2[4], bq3[2];
            ldsm4(a, aBase2 + ks * 32);
            ldsm4(bq0, bBase2 + ks * 32);
            ldsm4(bq1, bBase2 + 16 * MROW + ks * 32);
            ldsm4(bq2, bBase2 + 32 * MROW + ks * 32);
            if (wc == 0) ldsm2(bq3, bBase2 + 48 * MROW + ks * 32);
            mma16(d2[0][0], a, &bq0[0]);
            mma16(d2[0][1], a, &bq0[2]);
            mma16(d2[0][2], a, &bq1[0]);
            mma16(d2[0][3], a, &bq1[2]);
            mma16(d2[0][4], a, &bq2[0]);
            mma16(d2[0][5], a, &bq2[2]);
            if (wc == 0) mma16(d2[0][6], a, &bq3[0]);
        }
        __syncthreads();    // sync3: Ms reads done

        // ---- prefetch Ms(t+1); then wait W(t+1) before next GEMM1 ----
        if (tt + 1 < TPH) {
            issue_Ms(sb32, tid, t0 + tt + 1);
            CP_COMMIT();
            CP_WAIT1();     // W(t+1) done (Ms(t+1) may fly)
            __syncthreads();
        }
    }

    // ---- epilogue: atomic accumulate (2 adders/element onto 0 => determ.) --
#pragma unroll
    for (int e2 = 0; e2 < 2; e2++) {
        int row = rowBase + wr * 16 + g + e2 * 8;
        float* op = out + (size_t)row * CC;
#pragma unroll
        for (int ni = 0; ni < 7; ni++) {
            if (ni < nb2) {
                int col = wc * 56 + ni * 8 + 2 * tg;
                if (col < CC)     atomicAdd(op + col,     d2[0][ni][e2 * 2]);
                if (col + 1 < CC) atomicAdd(op + col + 1, d2[0][ni][e2 * 2 + 1]);
            }
        }
    }
}

// ---------------- launch -----------------------------------------------------
extern "C" void kernel_launch(void* const* d_in, const int* in_sizes, int n_in,
                              void* d_out, int out_size) {
    const float* x          = nullptr;   // 2097152
    const float* split_w    = nullptr;   // 516096
    const float* split_bias = nullptr;   // 2016
    const float* leaf_log   = nullptr;   // 204800
    const float* tree_w     = nullptr;   // 32
    const float* log_temp   = nullptr;   // 1
    for (int i = 0; i < n_in; i++) {
        switch (in_sizes[i]) {
            case BN * FF:      x          = (const float*)d_in[i]; break;
            case TT * NI * FF: split_w    = (const float*)d_in[i]; break;
            case TT * NI:      split_bias = (const float*)d_in[i]; break;
            case TT * NL * CC: leaf_log   = (const float*)d_in[i]; break;
            case TT:           tree_w     = (const float*)d_in[i]; break;
            case 1:            log_temp   = (const float*)d_in[i]; break;
            default: break;
        }
    }
    if (!x)          x          = (const float*)d_in[0];
    if (!split_w)    split_w    = (const float*)d_in[1];
    if (!split_bias) split_bias = (const float*)d_in[2];
    if (!leaf_log)   leaf_log   = (const float*)d_in[3];
    if (!tree_w)     tree_w     = (const float*)d_in[4];
    if (!log_temp)   log_temp   = (const float*)d_in[5];
    float* out = (float*)d_out;

    prep_kernel<<<TT * NL + TT, 128>>>(leaf_log, tree_w, log_temp, split_w);
    cudaMemsetAsync(out, 0, (size_t)out_size * sizeof(float), 0);

    cudaFuncSetAttribute(main_kernel,
                         cudaFuncAttributeMaxDynamicSharedMemorySize, SMEM_BYTES);
    dim3 grid(BN / BM, NHALF);
    main_kernel<<<grid, 256, SMEM_BYTES>>>(x, split_bias, out);
}